// round 13
// baseline (speedup 1.0000x reference)
#include <cuda_runtime.h>
#include <cuda_fp16.h>
#include <math.h>
#include <stdint.h>

#define CC 256
#define NN 4096
#define BB 16
#define NH 8
#define HD 32
#define HH 64
#define WW 64
#define M_QKV 768
#define SEGS 8

// ---------------- scratch (device globals; no allocation allowed) ----------------
__device__ float g_qkv[(size_t)BB * M_QKV * NN];   // (B, 768, N) fp32: q | k | v (q,k focused)
__device__ float g_kvp[SEGS * BB * NH * HD * HD];  // partial kv states
__device__ float g_ksp[SEGS * BB * NH * HD];       // partial ksums
__device__ float g_bcat[M_QKV];
__device__ float g_invscale[CC];
// fp16 buffers (uint4-typed for 16B alignment)
__device__ uint4 g_wh4 [M_QKV * CC * 2 / 16];              // W fp16
__device__ uint4 g_pwh4[CC * CC * 2 / 16];                 // Wproj fp16
__device__ uint4 g_xh4 [(size_t)BB * CC * NN * 2 / 16];    // x fp16
__device__ uint4 g_mh4 [(size_t)BB * CC * NN * 2 / 16];    // mid fp16

// ---------------- ptx helpers ----------------
__device__ __forceinline__ uint32_t smem_u32(const void* p) {
    uint32_t a;
    asm("{ .reg .u64 t; cvta.to.shared.u64 t, %1; cvt.u32.u64 %0, t; }" : "=r"(a) : "l"(p));
    return a;
}
__device__ __forceinline__ void cp_async16(uint32_t saddr, const void* gptr) {
    asm volatile("cp.async.cg.shared.global [%0], [%1], 16;"
                 :: "r"(saddr), "l"(__cvta_generic_to_global(gptr)) : "memory");
}
__device__ __forceinline__ void ldsm_x4(uint32_t* r, uint32_t addr) {
    asm volatile("ldmatrix.sync.aligned.m8n8.x4.shared.b16 {%0,%1,%2,%3}, [%4];"
                 : "=r"(r[0]), "=r"(r[1]), "=r"(r[2]), "=r"(r[3]) : "r"(addr));
}
__device__ __forceinline__ void ldsm_x4_t(uint32_t* r, uint32_t addr) {
    asm volatile("ldmatrix.sync.aligned.m8n8.x4.trans.shared.b16 {%0,%1,%2,%3}, [%4];"
                 : "=r"(r[0]), "=r"(r[1]), "=r"(r[2]), "=r"(r[3]) : "r"(addr));
}
__device__ __forceinline__ void mma_f16(float* c, const uint32_t* a, uint32_t b0, uint32_t b1) {
    asm volatile(
        "mma.sync.aligned.m16n8k16.row.col.f32.f16.f16.f32 "
        "{%0,%1,%2,%3}, {%4,%5,%6,%7}, {%8,%9}, {%0,%1,%2,%3};"
        : "+f"(c[0]), "+f"(c[1]), "+f"(c[2]), "+f"(c[3])
        : "r"(a[0]), "r"(a[1]), "r"(a[2]), "r"(a[3]), "r"(b0), "r"(b1));
}
// packed fp32x2 (plain sm_100+ PTX)
__device__ __forceinline__ unsigned long long pk2(float a, float b) {
    unsigned long long r;
    asm("mov.b64 %0, {%1, %2};" : "=l"(r) : "f"(a), "f"(b));
    return r;
}
__device__ __forceinline__ void upk2(unsigned long long v, float& a, float& b) {
    asm("mov.b64 {%0, %1}, %2;" : "=f"(a), "=f"(b) : "l"(v));
}
__device__ __forceinline__ unsigned long long fma2(unsigned long long a, unsigned long long b,
                                                   unsigned long long c) {
    unsigned long long d;
    asm("fma.rn.f32x2 %0, %1, %2, %3;" : "=l"(d) : "l"(a), "l"(b), "l"(c));
    return d;
}

// ---------------- prep ----------------
__global__ void prep_kernel(const float* __restrict__ Wq, const float* __restrict__ bq,
                            const float* __restrict__ Wkv, const float* __restrict__ bkv,
                            const float* __restrict__ Wproj, const float* __restrict__ scale_param) {
    int r = blockIdx.x, t = threadIdx.x;
    float w = (r < CC) ? Wq[(size_t)r * CC + t] : Wkv[(size_t)(r - CC) * CC + t];
    ((__half*)g_wh4)[(size_t)r * CC + t] = __float2half(w);
    if (r < CC)
        ((__half*)g_pwh4)[r * CC + t] = __float2half(Wproj[(size_t)r * CC + t]);
    if (t == 0) {
        g_bcat[r] = (r < CC) ? bq[r] : bkv[r - CC];
        if (r < CC) {
            float s = scale_param[r];
            float sp = (s > 20.f) ? s : log1pf(expf(s));
            g_invscale[r] = 1.0f / sp;
        }
    }
}

// ---------------- convert fp32 -> fp16 ----------------
__global__ __launch_bounds__(256)
void split_kernel(const float4* __restrict__ src, __half* __restrict__ dst, int n4) {
    int i = blockIdx.x * 256 + threadIdx.x;
    if (i >= n4) return;
    float4 v = src[i];
    __half2* dp = (__half2*)(dst + 4 * (size_t)i);
    dp[0] = __halves2half2(__float2half(v.x), __float2half(v.y));
    dp[1] = __halves2half2(__float2half(v.z), __float2half(v.w));
}

// ================= gemm1: all 3 parts per CTA, B persistent, in-reg focus =================
// 512 threads, 16 warps of 64x32. Flat 24-chunk loop (part = gc>>3), A 4-stage ring.
#define A1_STRIDE 80
#define B1_STRIDE 272
#define A1_TILE (256 * A1_STRIDE)            // 20480
#define B1_TILE (32 * B1_STRIDE)             // 8704
#define SMB 0
#define SMA (8 * B1_TILE)                    // 69632
#define SP2O (SMA + 4 * A1_TILE)             // 151552
#define SP6O (SP2O + 4224 * 4)               // 168448
#define SFO  (SP6O + 4224 * 4)               // 185344
#define SM_GEMM1 (SFO + 512)                 // 185856
#define STAGE1_BYTES (A1_TILE + B1_TILE)     // for gemm2
#define SM_GEMM2 (4 * STAGE1_BYTES)          // 116736
#define P_NCHUNK 8

__global__ __launch_bounds__(512)
void gemm1_fused_kernel(const __half* __restrict__ A, const __half* __restrict__ B,
                        float* __restrict__ out) {
    extern __shared__ char smem[];
    __shared__ float sb_all[768], sinv[256];
    uint32_t sb = smem_u32(smem);
    int tid = threadIdx.x, lane = tid & 31, wid = tid >> 5;
    int n0 = blockIdx.x * 128;
    int bz = blockIdx.z;
    int wm = (wid & 3) * 64;
    int wn = (wid >> 2) * 32;

    for (int i = tid; i < 768; i += 512) sb_all[i] = g_bcat[i];
    if (tid < 256) sinv[tid] = g_invscale[tid];

    const __half* Bb = B + (size_t)bz * CC * NN;

    float acc[4][4][4];
#pragma unroll
    for (int mt = 0; mt < 4; mt++)
#pragma unroll
        for (int nt = 0; nt < 4; nt++)
#pragma unroll
            for (int i = 0; i < 4; i++) acc[mt][nt][i] = 0.f;

    int a_row = tid >> 1, a_kc = (tid & 1) * 2;
    int b_row = tid >> 4, b_c = tid & 15;

    auto issueA = [&](int gc) {
        if (gc < 24) {
            int pt = gc >> 3, kb = (gc & 7) * 32;
            const __half* Ap = A + (size_t)pt * 256 * CC;
            uint32_t st = sb + SMA + (uint32_t)(gc & 3) * A1_TILE;
            cp_async16(st + a_row * A1_STRIDE + a_kc * 16,
                       Ap + (size_t)a_row * CC + kb + a_kc * 8);
            cp_async16(st + a_row * A1_STRIDE + (a_kc + 1) * 16,
                       Ap + (size_t)a_row * CC + kb + (a_kc + 1) * 8);
        }
        asm volatile("cp.async.commit_group;" ::: "memory");
    };

    // B persistent load (rides in group 0 with A chunk 0)
#pragma unroll
    for (int ck = 0; ck < 8; ck++)
        cp_async16(sb + SMB + (uint32_t)ck * B1_TILE + b_row * B1_STRIDE + b_c * 16,
                   Bb + (size_t)(ck * 32 + b_row) * NN + n0 + b_c * 8);
    issueA(0);
    issueA(1);
    issueA(2);

    int li = lane >> 3, lr = lane & 7;
    int g = lane >> 2, tg = lane & 3;
    float* sp2 = (float*)(smem + SP2O);
    float* sp6 = (float*)(smem + SP6O);
    float* sf  = (float*)(smem + SFO);

    for (int gc = 0; gc < 24; gc++) {
        asm volatile("cp.async.wait_group 2;" ::: "memory");
        __syncthreads();
        issueA(gc + 3);

        int ck = gc & 7;
        uint32_t stA = sb + SMA + (uint32_t)(gc & 3) * A1_TILE;
        uint32_t stB = sb + SMB + (uint32_t)ck * B1_TILE;
#pragma unroll
        for (int ks = 0; ks < 2; ks++) {
            uint32_t af[4][4];
#pragma unroll
            for (int mt = 0; mt < 4; mt++) {
                uint32_t addr = stA + (uint32_t)(wm + mt * 16 + (li & 1) * 8 + lr) * A1_STRIDE
                                    + (uint32_t)(ks * 32 + (li >> 1) * 16);
                ldsm_x4(af[mt], addr);
            }
#pragma unroll
            for (int j = 0; j < 2; j++) {
                uint32_t addr = stB + (uint32_t)(ks * 16 + (li & 1) * 8 + lr) * B1_STRIDE
                                    + (uint32_t)(wn + j * 16 + (li >> 1) * 8) * 2;
                uint32_t t4[4];
                ldsm_x4_t(t4, addr);
#pragma unroll
                for (int mt = 0; mt < 4; mt++) {
                    mma_f16(acc[mt][2 * j],     af[mt], t4[0], t4[1]);
                    mma_f16(acc[mt][2 * j + 1], af[mt], t4[2], t4[3]);
                }
            }
        }

        if (ck == 7) {
            int part = gc >> 3;
            if (part == 2) {
                // v: bias add, direct write
                float* ob = out + ((size_t)bz * M_QKV + 512) * NN + n0;
#pragma unroll
                for (int mt = 0; mt < 4; mt++) {
                    int m0 = wm + mt * 16 + g;
                    float bv0 = sb_all[512 + m0], bv1 = sb_all[512 + m0 + 8];
#pragma unroll
                    for (int nt = 0; nt < 4; nt++) {
                        int p0 = wn + nt * 8 + tg * 2;
                        *(float2*)(ob + (size_t)m0 * NN + p0) =
                            make_float2(acc[mt][nt][0] + bv0, acc[mt][nt][1] + bv0);
                        *(float2*)(ob + (size_t)(m0 + 8) * NN + p0) =
                            make_float2(acc[mt][nt][2] + bv1, acc[mt][nt][3] + bv1);
                    }
                }
            } else {
                // q/k: in-register focus epilogue
                float s2l[8], s6l[8];
#pragma unroll
                for (int pl = 0; pl < 8; pl++) { s2l[pl] = 0.f; s6l[pl] = 0.f; }
#pragma unroll
                for (int mt = 0; mt < 4; mt++)
#pragma unroll
                    for (int nt = 0; nt < 4; nt++)
#pragma unroll
                        for (int i = 0; i < 4; i++) {
                            int m = wm + mt * 16 + g + 8 * (i >> 1);
                            float v = acc[mt][nt][i] + sb_all[part * 256 + m];
                            v = fmaxf(v, 0.f) + 1e-6f;
                            v *= sinv[m];
                            float v3 = v * v * v;
                            acc[mt][nt][i] = v3;
                            int pl = nt * 2 + (i & 1);
                            s2l[pl] += v * v;
                            s6l[pl] += v3 * v3;
                        }
                __syncthreads();
                int r = (wid & 3) * 8 + g;
#pragma unroll
                for (int pl = 0; pl < 8; pl++) {
                    int p = wn + (pl >> 1) * 8 + tg * 2 + (pl & 1);
                    sp2[p * 33 + r] = s2l[pl];
                    sp6[p * 33 + r] = s6l[pl];
                }
                __syncthreads();
                if (tid < 128) {
                    float t2 = 0.f, t6 = 0.f;
#pragma unroll
                    for (int r2 = 0; r2 < 32; r2++) {
                        t2 += sp2[tid * 33 + r2];
                        t6 += sp6[tid * 33 + r2];
                    }
                    sf[tid] = sqrtf(t2 / t6);
                }
                __syncthreads();
                float* ob = out + ((size_t)bz * M_QKV + part * 256) * NN + n0;
#pragma unroll
                for (int mt = 0; mt < 4; mt++) {
                    int m0 = wm + mt * 16 + g;
#pragma unroll
                    for (int nt = 0; nt < 4; nt++) {
                        int p0 = wn + nt * 8 + tg * 2;
                        float f0 = sf[p0], f1 = sf[p0 + 1];
                        *(float2*)(ob + (size_t)m0 * NN + p0) =
                            make_float2(acc[mt][nt][0] * f0, acc[mt][nt][1] * f1);
                        *(float2*)(ob + (size_t)(m0 + 8) * NN + p0) =
                            make_float2(acc[mt][nt][2] * f0, acc[mt][nt][3] * f1);
                    }
                }
            }
            // reset accumulators for the next part
#pragma unroll
            for (int mt = 0; mt < 4; mt++)
#pragma unroll
                for (int nt = 0; nt < 4; nt++)
#pragma unroll
                    for (int i = 0; i < 4; i++) acc[mt][nt][i] = 0.f;
        }
    }
}

// ---------------- gemm2 wide: 512 threads, 256x128 tile, plain epilogue ----------------
__global__ __launch_bounds__(512)
void gemm2_wide_kernel(const __half* __restrict__ A, const __half* __restrict__ B,
                       const float* __restrict__ bias, float* __restrict__ out) {
    extern __shared__ char smem[];
    __shared__ float sbias[256];
    uint32_t sb = smem_u32(smem);
    int tid = threadIdx.x, lane = tid & 31, wid = tid >> 5;
    int n0 = blockIdx.x * 128;
    int bz = blockIdx.z;
    int wm = (wid & 3) * 64;
    int wn = (wid >> 2) * 32;

    if (tid < 256) sbias[tid] = bias[tid];

    const __half* Bb = B + (size_t)bz * CC * NN;

    float acc[4][4][4];
#pragma unroll
    for (int mt = 0; mt < 4; mt++)
#pragma unroll
        for (int nt = 0; nt < 4; nt++)
#pragma unroll
            for (int i = 0; i < 4; i++) acc[mt][nt][i] = 0.f;

    int a_row = tid >> 1, a_kc = (tid & 1) * 2;
    int b_row = tid >> 4, b_c = tid & 15;

    auto issue_load = [&](int ck) {
        if (ck < P_NCHUNK) {
            int kb = ck * 32;
            uint32_t st = sb + (uint32_t)(ck & 3) * STAGE1_BYTES;
            cp_async16(st + a_row * A1_STRIDE + a_kc * 16,
                       A + (size_t)a_row * CC + kb + a_kc * 8);
            cp_async16(st + a_row * A1_STRIDE + (a_kc + 1) * 16,
                       A + (size_t)a_row * CC + kb + (a_kc + 1) * 8);
            cp_async16(st + A1_TILE + b_row * B1_STRIDE + b_c * 16,
                       Bb + (size_t)(kb + b_row) * NN + n0 + b_c * 8);
        }
        asm volatile("cp.async.commit_group;" ::: "memory");
    };

    issue_load(0);
    issue_load(1);
    issue_load(2);

    int li = lane >> 3, lr = lane & 7;

    for (int ck = 0; ck < P_NCHUNK; ck++) {
        asm volatile("cp.async.wait_group 2;" ::: "memory");
        __syncthreads();
        issue_load(ck + 3);

        uint32_t st = sb + (uint32_t)(ck & 3) * STAGE1_BYTES;
#pragma unroll
        for (int ks = 0; ks < 2; ks++) {
            uint32_t af[4][4];
#pragma unroll
            for (int mt = 0; mt < 4; mt++) {
                uint32_t addr = st + (uint32_t)(wm + mt * 16 + (li & 1) * 8 + lr) * A1_STRIDE
                                   + (uint32_t)(ks * 32 + (li >> 1) * 16);
                ldsm_x4(af[mt], addr);
            }
#pragma unroll
            for (int j = 0; j < 2; j++) {
                uint32_t addr = st + A1_TILE
                              + (uint32_t)(ks * 16 + (li & 1) * 8 + lr) * B1_STRIDE
                              + (uint32_t)(wn + j * 16 + (li >> 1) * 8) * 2;
                uint32_t t4[4];
                ldsm_x4_t(t4, addr);
#pragma unroll
                for (int mt = 0; mt < 4; mt++) {
                    mma_f16(acc[mt][2 * j],     af[mt], t4[0], t4[1]);
                    mma_f16(acc[mt][2 * j + 1], af[mt], t4[2], t4[3]);
                }
            }
        }
        __syncthreads();
    }

    int g = lane >> 2, tg = lane & 3;
    float* ob = out + (size_t)bz * CC * NN + n0;
#pragma unroll
    for (int mt = 0; mt < 4; mt++) {
        int m0 = wm + mt * 16 + g;
        float bv0 = sbias[m0], bv1 = sbias[m0 + 8];
#pragma unroll
        for (int nt = 0; nt < 4; nt++) {
            int nl = wn + nt * 8 + tg * 2;
            *(float2*)(ob + (size_t)m0 * NN + nl) =
                make_float2(acc[mt][nt][0] + bv0, acc[mt][nt][1] + bv0);
            *(float2*)(ob + (size_t)(m0 + 8) * NN + nl) =
                make_float2(acc[mt][nt][2] + bv1, acc[mt][nt][3] + bv1);
        }
    }
}

// ---------------- per-head kv_state partials: 4x4 reg tiles + hoisted XOR swizzle ----------------
#define CHUNK 128
#define JSTR 36
__global__ __launch_bounds__(256)
void kvstate_kernel() {
    int bh = blockIdx.x, seg = blockIdx.y;
    int b = bh >> 3, h = bh & 7;
    const float* kbase = g_qkv + ((size_t)b * M_QKV + CC + h * HD) * NN;
    const float* vbase = g_qkv + ((size_t)b * M_QKV + 2 * CC + h * HD) * NN;
    __shared__ __align__(16) float sk[CHUNK * JSTR];
    __shared__ __align__(16) float sv[CHUNK * JSTR];
    int tid = threadIdx.x;
    int t = tid & 63, s = tid >> 6;
    int c4 = (t >> 3) * 4, d4 = (t & 7) * 4;
    int lc = tid >> 3, lj4 = (tid & 7) * 4;
    float a00=0,a01=0,a02=0,a03=0, a10=0,a11=0,a12=0,a13=0;
    float a20=0,a21=0,a22=0,a23=0, a30=0,a31=0,a32=0,a33=0;
    float ks0=0, ks1=0, ks2=0, ks3=0;
    int j_begin = seg * (NN / SEGS);

    for (int j0 = j_begin; j0 < j_begin + NN / SEGS; j0 += CHUNK) {
#pragma unroll
        for (int jj = 0; jj < CHUNK; jj += 32) {
            float4 k4 = *(const float4*)(kbase + (size_t)lc * NN + j0 + jj + lj4);
            float4 v4 = *(const float4*)(vbase + (size_t)lc * NN + j0 + jj + lj4);
            int jr = jj + lj4;
            int xv = ((jr >> 2) & 7) * 4;
            int lcs = lc ^ xv;
            sk[(jr + 0) * JSTR + lcs] = k4.x;
            sk[(jr + 1) * JSTR + lcs] = k4.y;
            sk[(jr + 2) * JSTR + lcs] = k4.z;
            sk[(jr + 3) * JSTR + lcs] = k4.w;
            sv[(jr + 0) * JSTR + lcs] = v4.x;
            sv[(jr + 1) * JSTR + lcs] = v4.y;
            sv[(jr + 2) * JSTR + lcs] = v4.z;
            sv[(jr + 3) * JSTR + lcs] = v4.w;
        }
        __syncthreads();
        int jb = s * 32;
#pragma unroll
        for (int jg = 0; jg < 32; jg += 4) {
            int jrow = jb + jg;
            int xv = ((jrow >> 2) & 7) * 4;
            const float* skp = sk + (size_t)jrow * JSTR + (c4 ^ xv);
            const float* svp = sv + (size_t)jrow * JSTR + (d4 ^ xv);
#pragma unroll
            for (int u = 0; u < 4; u++) {
                float4 kq = *(const float4*)(skp + u * JSTR);
                float4 vq = *(const float4*)(svp + u * JSTR);
                a00 += kq.x * vq.x; a01 += kq.x * vq.y; a02 += kq.x * vq.z; a03 += kq.x * vq.w;
                a10 += kq.y * vq.x; a11 += kq.y * vq.y; a12 += kq.y * vq.z; a13 += kq.y * vq.w;
                a20 += kq.z * vq.x; a21 += kq.z * vq.y; a22 += kq.z * vq.z; a23 += kq.z * vq.w;
                a30 += kq.w * vq.x; a31 += kq.w * vq.y; a32 += kq.w * vq.z; a33 += kq.w * vq.w;
                if (d4 == 0) { ks0 += kq.x; ks1 += kq.y; ks2 += kq.z; ks3 += kq.w; }
            }
        }
        __syncthreads();
    }

    float accf[16] = {a00,a01,a02,a03, a10,a11,a12,a13, a20,a21,a22,a23, a30,a31,a32,a33};
#pragma unroll
    for (int i = 0; i < 16; i++) sk[tid * 16 + i] = accf[i];
    if (d4 == 0) {
        sv[(s * 8 + (t >> 3)) * 4 + 0] = ks0;
        sv[(s * 8 + (t >> 3)) * 4 + 1] = ks1;
        sv[(s * 8 + (t >> 3)) * 4 + 2] = ks2;
        sv[(s * 8 + (t >> 3)) * 4 + 3] = ks3;
    }
    __syncthreads();
    if (tid < 64) {
        float* kvs = g_kvp + ((size_t)seg * BB * NH + bh) * HD * HD;
        int cc4 = (tid >> 3) * 4, dd4 = (tid & 7) * 4;
#pragma unroll
        for (int i = 0; i < 16; i++) {
            float r = sk[tid * 16 + i] + sk[(64 + tid) * 16 + i]
                    + sk[(128 + tid) * 16 + i] + sk[(192 + tid) * 16 + i];
            kvs[(cc4 + (i >> 2)) * HD + dd4 + (i & 3)] = r;
        }
        if ((tid & 7) == 0) {
            int gq = tid >> 3;
#pragma unroll
            for (int i = 0; i < 4; i++) {
                float r = sv[gq * 4 + i] + sv[(8 + gq) * 4 + i]
                        + sv[(16 + gq) * 4 + i] + sv[(24 + gq) * 4 + i];
                g_ksp[((size_t)seg * BB * NH + bh) * HD + cc4 + i] = r;
            }
        }
    }
}

// ---------------- fused depthwise conv + attention output (f32x2 packed) -> fp16 mid ----------------
__global__ __launch_bounds__(256)
void conv_attn_kernel(const float* __restrict__ dwc_w, const float* __restrict__ dwc_b) {
    __shared__ float skvs[HD * HD];
    __shared__ float sks[HD];
    __shared__ __align__(8) float2 tile2[2][20][21];
    __shared__ __align__(8) float2 wloc2[2][25];
    int bh = blockIdx.y;
    int b = bh >> 3, h = bh & 7;
    int ty0 = (blockIdx.x >> 2) * 16;
    int tx0 = (blockIdx.x & 3) * 16;
    int tid = threadIdx.x, lx = tid & 15, ly = tid >> 4;
    int gy = ty0 + ly, gx = tx0 + lx;
    int n = gy * WW + gx;

    for (int i = tid; i < HD * HD; i += 256) {
        float s = 0.f;
#pragma unroll
        for (int seg = 0; seg < SEGS; seg++)
            s += g_kvp[((size_t)seg * BB * NH + bh) * HD * HD + i];
        skvs[i] = s;
    }
    if (tid < HD) {
        float s = 0.f;
#pragma unroll
        for (int seg = 0; seg < SEGS; seg++)
            s += g_ksp[((size_t)seg * BB * NH + bh) * HD + tid];
        sks[tid] = s;
    }

    unsigned long long accC[16];
    const float* vball = g_qkv + ((size_t)b * M_QKV + 2 * CC + h * HD) * NN;
    for (int d0 = 0; d0 < HD; d0 += 4) {
        __syncthreads();
        if (tid < 50) {
            int p = tid / 25, i = tid % 25;
            wloc2[p][i] = make_float2(dwc_w[(d0 + 2 * p) * 25 + i],
                                      dwc_w[(d0 + 2 * p + 1) * 25 + i]);
        }
        for (int i = tid; i < 800; i += 256) {
            int p = i / 400, r = i % 400;
            int ry = r / 20, rx = r % 20;
            int sy = ty0 - 2 + ry, sx = tx0 - 2 + rx;
            float2 v = make_float2(0.f, 0.f);
            if (sy >= 0 && sy < HH && sx >= 0 && sx < WW) {
                v.x = vball[(size_t)(d0 + 2 * p) * NN + sy * WW + sx];
                v.y = vball[(size_t)(d0 + 2 * p + 1) * NN + sy * WW + sx];
            }
            tile2[p][ry][rx] = v;
        }
        __syncthreads();
#pragma unroll
        for (int p = 0; p < 2; p++) {
            unsigned long long a = pk2(dwc_b[d0 + 2 * p], dwc_b[d0 + 2 * p + 1]);
#pragma unroll
            for (int ky = 0; ky < 5; ky++)
#pragma unroll
                for (int kx = 0; kx < 5; kx++)
                    a = fma2(*(const unsigned long long*)&tile2[p][ly + ky][lx + kx],
                             *(const unsigned long long*)&wloc2[p][ky * 5 + kx], a);
            accC[d0 / 2 + p] = a;
        }
    }
    __syncthreads();

    const float* qbase = g_qkv + ((size_t)b * M_QKV + h * HD) * NN + n;
    unsigned long long acc2[16];
#pragma unroll
    for (int i = 0; i < 16; i++) acc2[i] = 0ull;
    float zacc = 0.f;
#pragma unroll
    for (int c = 0; c < HD; c++) {
        float qv = qbase[(size_t)c * NN];
        zacc += qv * sks[c];
        unsigned long long q2 = pk2(qv, qv);
        const unsigned long long* row = (const unsigned long long*)&skvs[c * HD];
#pragma unroll
        for (int d2 = 0; d2 < 16; d2++)
            acc2[d2] = fma2(q2, row[d2], acc2[d2]);
    }
    float z = 1.0f / (zacc + 1e-6f);
    unsigned long long z2 = pk2(z, z);
    __half* mh = (__half*)g_mh4;
#pragma unroll
    for (int d2 = 0; d2 < 16; d2++) {
        unsigned long long r = fma2(acc2[d2], z2, accC[d2]);
        float r0, r1;
        upk2(r, r0, r1);
        size_t off = ((size_t)b * CC + h * HD + 2 * d2) * NN + n;
        mh[off] = __float2half(r0);
        mh[off + NN] = __float2half(r1);
    }
}

// ---------------- launch ----------------
extern "C" void kernel_launch(void* const* d_in, const int* in_sizes, int n_in,
                              void* d_out, int out_size) {
    const float* x           = (const float*)d_in[0];
    const float* Wq          = (const float*)d_in[1];
    const float* bq          = (const float*)d_in[2];
    const float* Wkv         = (const float*)d_in[3];
    const float* bkv         = (const float*)d_in[4];
    const float* Wproj       = (const float*)d_in[5];
    const float* bproj       = (const float*)d_in[6];
    const float* dwc_w       = (const float*)d_in[7];
    const float* dwc_b       = (const float*)d_in[8];
    const float* scale_param = (const float*)d_in[9];
    float* out = (float*)d_out;

    float *p_qkv;
    uint4 *p_wh, *p_pwh, *p_xh, *p_mh;
    cudaGetSymbolAddress((void**)&p_qkv,  g_qkv);
    cudaGetSymbolAddress((void**)&p_wh,   g_wh4);
    cudaGetSymbolAddress((void**)&p_pwh,  g_pwh4);
    cudaGetSymbolAddress((void**)&p_xh,   g_xh4);
    cudaGetSymbolAddress((void**)&p_mh,   g_mh4);

    cudaFuncSetAttribute(gemm1_fused_kernel, cudaFuncAttributeMaxDynamicSharedMemorySize, SM_GEMM1);
    cudaFuncSetAttribute(gemm2_wide_kernel, cudaFuncAttributeMaxDynamicSharedMemorySize, SM_GEMM2);

    prep_kernel<<<M_QKV, CC>>>(Wq, bq, Wkv, bkv, Wproj, scale_param);

    int n4 = BB * CC * NN / 4;
    split_kernel<<<(n4 + 255) / 256, 256>>>((const float4*)x, (__half*)p_xh, n4);

    // QKV projection (all 3 parts per CTA) + focus fused: grid (32 pixel-tiles, 16 batches)
    gemm1_fused_kernel<<<dim3(NN / 128, 1, BB), 512, SM_GEMM1>>>(
        (const __half*)p_wh, (const __half*)p_xh, p_qkv);

    kvstate_kernel<<<dim3(BB * NH, SEGS), 256>>>();

    conv_attn_kernel<<<dim3(16, BB * NH), 256>>>(dwc_w, dwc_b);

    // Output projection: 256x256 @ 256x4096 per batch -> d_out (256x128 tiles)
    gemm2_wide_kernel<<<dim3(NN / 128, 1, BB), 512, SM_GEMM2>>>(
        (const __half*)p_pwh, (const __half*)p_mh, bproj, out);
}

// round 14
// speedup vs baseline: 1.0612x; 1.0612x over previous
#include <cuda_runtime.h>
#include <cuda_fp16.h>
#include <math.h>
#include <stdint.h>

#define CC 256
#define NN 4096
#define BB 16
#define NH 8
#define HD 32
#define HH 64
#define WW 64
#define M_QKV 768
#define SEGS 8

// ---------------- scratch (device globals; no allocation allowed) ----------------
__device__ float g_qkv[(size_t)BB * M_QKV * NN];   // (B, 768, N) fp32: q | k | v (q,k focused)
__device__ float g_kvp[SEGS * BB * NH * HD * HD];  // partial kv states
__device__ float g_ksp[SEGS * BB * NH * HD];       // partial ksums
__device__ float g_bcat[M_QKV];
__device__ float g_invscale[CC];
// fp16 buffers (uint4-typed for 16B alignment)
__device__ uint4 g_wh4 [M_QKV * CC * 2 / 16];              // W fp16
__device__ uint4 g_pwh4[CC * CC * 2 / 16];                 // Wproj fp16
__device__ uint4 g_xh4 [(size_t)BB * CC * NN * 2 / 16];    // x fp16
__device__ uint4 g_mh4 [(size_t)BB * CC * NN * 2 / 16];    // mid fp16

// ---------------- ptx helpers ----------------
__device__ __forceinline__ uint32_t smem_u32(const void* p) {
    uint32_t a;
    asm("{ .reg .u64 t; cvta.to.shared.u64 t, %1; cvt.u32.u64 %0, t; }" : "=r"(a) : "l"(p));
    return a;
}
__device__ __forceinline__ void cp_async16(uint32_t saddr, const void* gptr) {
    asm volatile("cp.async.cg.shared.global [%0], [%1], 16;"
                 :: "r"(saddr), "l"(__cvta_generic_to_global(gptr)) : "memory");
}
__device__ __forceinline__ void ldsm_x4(uint32_t* r, uint32_t addr) {
    asm volatile("ldmatrix.sync.aligned.m8n8.x4.shared.b16 {%0,%1,%2,%3}, [%4];"
                 : "=r"(r[0]), "=r"(r[1]), "=r"(r[2]), "=r"(r[3]) : "r"(addr));
}
__device__ __forceinline__ void ldsm_x4_t(uint32_t* r, uint32_t addr) {
    asm volatile("ldmatrix.sync.aligned.m8n8.x4.trans.shared.b16 {%0,%1,%2,%3}, [%4];"
                 : "=r"(r[0]), "=r"(r[1]), "=r"(r[2]), "=r"(r[3]) : "r"(addr));
}
__device__ __forceinline__ void mma_f16(float* c, const uint32_t* a, uint32_t b0, uint32_t b1) {
    asm volatile(
        "mma.sync.aligned.m16n8k16.row.col.f32.f16.f16.f32 "
        "{%0,%1,%2,%3}, {%4,%5,%6,%7}, {%8,%9}, {%0,%1,%2,%3};"
        : "+f"(c[0]), "+f"(c[1]), "+f"(c[2]), "+f"(c[3])
        : "r"(a[0]), "r"(a[1]), "r"(a[2]), "r"(a[3]), "r"(b0), "r"(b1));
}
// packed fp32x2 (plain sm_100+ PTX)
__device__ __forceinline__ unsigned long long pk2(float a, float b) {
    unsigned long long r;
    asm("mov.b64 %0, {%1, %2};" : "=l"(r) : "f"(a), "f"(b));
    return r;
}
__device__ __forceinline__ void upk2(unsigned long long v, float& a, float& b) {
    asm("mov.b64 {%0, %1}, %2;" : "=f"(a), "=f"(b) : "l"(v));
}
__device__ __forceinline__ unsigned long long fma2(unsigned long long a, unsigned long long b,
                                                   unsigned long long c) {
    unsigned long long d;
    asm("fma.rn.f32x2 %0, %1, %2, %3;" : "=l"(d) : "l"(a), "l"(b), "l"(c));
    return d;
}

// ---------------- prep ----------------
__global__ void prep_kernel(const float* __restrict__ Wq, const float* __restrict__ bq,
                            const float* __restrict__ Wkv, const float* __restrict__ bkv,
                            const float* __restrict__ Wproj, const float* __restrict__ scale_param) {
    int r = blockIdx.x, t = threadIdx.x;
    float w = (r < CC) ? Wq[(size_t)r * CC + t] : Wkv[(size_t)(r - CC) * CC + t];
    ((__half*)g_wh4)[(size_t)r * CC + t] = __float2half(w);
    if (r < CC)
        ((__half*)g_pwh4)[r * CC + t] = __float2half(Wproj[(size_t)r * CC + t]);
    if (t == 0) {
        g_bcat[r] = (r < CC) ? bq[r] : bkv[r - CC];
        if (r < CC) {
            float s = scale_param[r];
            float sp = (s > 20.f) ? s : log1pf(expf(s));
            g_invscale[r] = 1.0f / sp;
        }
    }
}

// ---------------- convert fp32 -> fp16 ----------------
__global__ __launch_bounds__(256)
void split_kernel(const float4* __restrict__ src, __half* __restrict__ dst, int n4) {
    int i = blockIdx.x * 256 + threadIdx.x;
    if (i >= n4) return;
    float4 v = src[i];
    __half2* dp = (__half2*)(dst + 4 * (size_t)i);
    dp[0] = __halves2half2(__float2half(v.x), __float2half(v.y));
    dp[1] = __halves2half2(__float2half(v.z), __float2half(v.w));
}

// ================= gemm1 fused: qkv projection + in-register focus epilogue =================
// 512 threads, CTA 256 channels x 128 pixels, 16 warps of 64x32, 3-stage ring (2 CTAs/SM).
// grid (32 pixel-tiles, part 0=q/1=k/2=v, batch).
#define P_NCHUNK 8
#define A1_STRIDE 80
#define B1_STRIDE 272
#define A1_TILE (256 * A1_STRIDE)            // 20480
#define B1_TILE (32 * B1_STRIDE)             // 8704
#define STAGE1_BYTES (A1_TILE + B1_TILE)     // 29184
#define SM_GEMM (3 * STAGE1_BYTES)           // 87552 -> 2 CTAs/SM
// epilogue overlay offsets (within the 87.5KB dynamic smem, used after mainloop)
#define SP2O 0
#define SP6O (128 * 33 * 4)                  // 16896
#define SFO  (2 * 128 * 33 * 4)              // 33792

__global__ __launch_bounds__(512)
void gemm1_fused_kernel(const __half* __restrict__ A, const __half* __restrict__ B,
                        float* __restrict__ out) {
    extern __shared__ char smem[];
    __shared__ float ssinv[256], sbias[256];
    uint32_t sb = smem_u32(smem);
    int tid = threadIdx.x, lane = tid & 31, wid = tid >> 5;
    int n0 = blockIdx.x * 128;
    int part = blockIdx.y;
    int bz = blockIdx.z;
    int wm = (wid & 3) * 64;
    int wn = (wid >> 2) * 32;

    if (tid < 256) {
        sbias[tid] = g_bcat[part * 256 + tid];
        if (part < 2) ssinv[tid] = g_invscale[tid];
    }

    const __half* Am = A + (size_t)part * 256 * CC;
    const __half* Bb = B + (size_t)bz * CC * NN;

    float acc[4][4][4];
#pragma unroll
    for (int mt = 0; mt < 4; mt++)
#pragma unroll
        for (int nt = 0; nt < 4; nt++)
#pragma unroll
            for (int i = 0; i < 4; i++) acc[mt][nt][i] = 0.f;

    int a_row = tid >> 1, a_kc = (tid & 1) * 2;
    int b_row = tid >> 4, b_c = tid & 15;

    auto issue_load = [&](int ck) {
        if (ck < P_NCHUNK) {
            int kb = ck * 32;
            uint32_t st = sb + (uint32_t)(ck % 3) * STAGE1_BYTES;
            cp_async16(st + a_row * A1_STRIDE + a_kc * 16,
                       Am + (size_t)a_row * CC + kb + a_kc * 8);
            cp_async16(st + a_row * A1_STRIDE + (a_kc + 1) * 16,
                       Am + (size_t)a_row * CC + kb + (a_kc + 1) * 8);
            cp_async16(st + A1_TILE + b_row * B1_STRIDE + b_c * 16,
                       Bb + (size_t)(kb + b_row) * NN + n0 + b_c * 8);
        }
        asm volatile("cp.async.commit_group;" ::: "memory");
    };

    issue_load(0);
    issue_load(1);

    int li = lane >> 3, lr = lane & 7;

    for (int ck = 0; ck < P_NCHUNK; ck++) {
        asm volatile("cp.async.wait_group 1;" ::: "memory");
        __syncthreads();
        issue_load(ck + 2);

        uint32_t st = sb + (uint32_t)(ck % 3) * STAGE1_BYTES;
#pragma unroll
        for (int ks = 0; ks < 2; ks++) {
            uint32_t af[4][4];
#pragma unroll
            for (int mt = 0; mt < 4; mt++) {
                uint32_t addr = st + (uint32_t)(wm + mt * 16 + (li & 1) * 8 + lr) * A1_STRIDE
                                   + (uint32_t)(ks * 32 + (li >> 1) * 16);
                ldsm_x4(af[mt], addr);
            }
#pragma unroll
            for (int j = 0; j < 2; j++) {
                uint32_t addr = st + A1_TILE
                              + (uint32_t)(ks * 16 + (li & 1) * 8 + lr) * B1_STRIDE
                              + (uint32_t)(wn + j * 16 + (li >> 1) * 8) * 2;
                uint32_t t4[4];
                ldsm_x4_t(t4, addr);
#pragma unroll
                for (int mt = 0; mt < 4; mt++) {
                    mma_f16(acc[mt][2 * j],     af[mt], t4[0], t4[1]);
                    mma_f16(acc[mt][2 * j + 1], af[mt], t4[2], t4[3]);
                }
            }
        }
    }

    int g = lane >> 2, tg = lane & 3;

    if (part == 2) {
        float* ob = out + ((size_t)bz * M_QKV + 512) * NN + n0;
#pragma unroll
        for (int mt = 0; mt < 4; mt++) {
            int m0 = wm + mt * 16 + g;
            float bv0 = sbias[m0], bv1 = sbias[m0 + 8];
#pragma unroll
            for (int nt = 0; nt < 4; nt++) {
                int nl = wn + nt * 8 + tg * 2;
                *(float2*)(ob + (size_t)m0 * NN + nl) =
                    make_float2(acc[mt][nt][0] + bv0, acc[mt][nt][1] + bv0);
                *(float2*)(ob + (size_t)(m0 + 8) * NN + nl) =
                    make_float2(acc[mt][nt][2] + bv1, acc[mt][nt][3] + bv1);
            }
        }
        return;
    }

    // q/k: in-register focus epilogue; sp2/sp6/sf overlay stage smem (after mainloop reads)
    float* sp2 = (float*)(smem + SP2O);
    float* sp6 = (float*)(smem + SP6O);
    float* sf  = (float*)(smem + SFO);
    float s2l[8], s6l[8];
#pragma unroll
    for (int pl = 0; pl < 8; pl++) { s2l[pl] = 0.f; s6l[pl] = 0.f; }
#pragma unroll
    for (int mt = 0; mt < 4; mt++)
#pragma unroll
        for (int nt = 0; nt < 4; nt++)
#pragma unroll
            for (int i = 0; i < 4; i++) {
                int m = wm + mt * 16 + g + 8 * (i >> 1);
                float v = acc[mt][nt][i] + sbias[m];
                v = fmaxf(v, 0.f) + 1e-6f;
                v *= ssinv[m];
                float v3 = v * v * v;
                acc[mt][nt][i] = v3;
                int pl = nt * 2 + (i & 1);
                s2l[pl] += v * v;
                s6l[pl] += v3 * v3;
            }
    __syncthreads();   // mainloop smem reads done before overlay writes
    int r = (wid & 3) * 8 + g;
#pragma unroll
    for (int pl = 0; pl < 8; pl++) {
        int p = wn + (pl >> 1) * 8 + tg * 2 + (pl & 1);
        sp2[p * 33 + r] = s2l[pl];
        sp6[p * 33 + r] = s6l[pl];
    }
    __syncthreads();
    if (tid < 128) {
        float t2 = 0.f, t6 = 0.f;
#pragma unroll
        for (int r2 = 0; r2 < 32; r2++) {
            t2 += sp2[tid * 33 + r2];
            t6 += sp6[tid * 33 + r2];
        }
        sf[tid] = sqrtf(t2 / t6);
    }
    __syncthreads();
    float* ob = out + ((size_t)bz * M_QKV + part * 256) * NN + n0;
#pragma unroll
    for (int mt = 0; mt < 4; mt++) {
        int m0 = wm + mt * 16 + g;
#pragma unroll
        for (int nt = 0; nt < 4; nt++) {
            int p0 = wn + nt * 8 + tg * 2;
            float f0 = sf[p0], f1 = sf[p0 + 1];
            *(float2*)(ob + (size_t)m0 * NN + p0) =
                make_float2(acc[mt][nt][0] * f0, acc[mt][nt][1] * f1);
            *(float2*)(ob + (size_t)(m0 + 8) * NN + p0) =
                make_float2(acc[mt][nt][2] * f0, acc[mt][nt][3] * f1);
        }
    }
}

// ---------------- gemm2 wide: 512 threads, 256x128 tile, 3-stage ring ----------------
__global__ __launch_bounds__(512)
void gemm2_wide_kernel(const __half* __restrict__ A, const __half* __restrict__ B,
                       const float* __restrict__ bias, float* __restrict__ out) {
    extern __shared__ char smem[];
    __shared__ float sbias[256];
    uint32_t sb = smem_u32(smem);
    int tid = threadIdx.x, lane = tid & 31, wid = tid >> 5;
    int n0 = blockIdx.x * 128;
    int bz = blockIdx.z;
    int wm = (wid & 3) * 64;
    int wn = (wid >> 2) * 32;

    if (tid < 256) sbias[tid] = bias[tid];

    const __half* Bb = B + (size_t)bz * CC * NN;

    float acc[4][4][4];
#pragma unroll
    for (int mt = 0; mt < 4; mt++)
#pragma unroll
        for (int nt = 0; nt < 4; nt++)
#pragma unroll
            for (int i = 0; i < 4; i++) acc[mt][nt][i] = 0.f;

    int a_row = tid >> 1, a_kc = (tid & 1) * 2;
    int b_row = tid >> 4, b_c = tid & 15;

    auto issue_load = [&](int ck) {
        if (ck < P_NCHUNK) {
            int kb = ck * 32;
            uint32_t st = sb + (uint32_t)(ck % 3) * STAGE1_BYTES;
            cp_async16(st + a_row * A1_STRIDE + a_kc * 16,
                       A + (size_t)a_row * CC + kb + a_kc * 8);
            cp_async16(st + a_row * A1_STRIDE + (a_kc + 1) * 16,
                       A + (size_t)a_row * CC + kb + (a_kc + 1) * 8);
            cp_async16(st + A1_TILE + b_row * B1_STRIDE + b_c * 16,
                       Bb + (size_t)(kb + b_row) * NN + n0 + b_c * 8);
        }
        asm volatile("cp.async.commit_group;" ::: "memory");
    };

    issue_load(0);
    issue_load(1);

    int li = lane >> 3, lr = lane & 7;

    for (int ck = 0; ck < P_NCHUNK; ck++) {
        asm volatile("cp.async.wait_group 1;" ::: "memory");
        __syncthreads();
        issue_load(ck + 2);

        uint32_t st = sb + (uint32_t)(ck % 3) * STAGE1_BYTES;
#pragma unroll
        for (int ks = 0; ks < 2; ks++) {
            uint32_t af[4][4];
#pragma unroll
            for (int mt = 0; mt < 4; mt++) {
                uint32_t addr = st + (uint32_t)(wm + mt * 16 + (li & 1) * 8 + lr) * A1_STRIDE
                                   + (uint32_t)(ks * 32 + (li >> 1) * 16);
                ldsm_x4(af[mt], addr);
            }
#pragma unroll
            for (int j = 0; j < 2; j++) {
                uint32_t addr = st + A1_TILE
                              + (uint32_t)(ks * 16 + (li & 1) * 8 + lr) * B1_STRIDE
                              + (uint32_t)(wn + j * 16 + (li >> 1) * 8) * 2;
                uint32_t t4[4];
                ldsm_x4_t(t4, addr);
#pragma unroll
                for (int mt = 0; mt < 4; mt++) {
                    mma_f16(acc[mt][2 * j],     af[mt], t4[0], t4[1]);
                    mma_f16(acc[mt][2 * j + 1], af[mt], t4[2], t4[3]);
                }
            }
        }
    }

    int g = lane >> 2, tg = lane & 3;
    float* ob = out + (size_t)bz * CC * NN + n0;
#pragma unroll
    for (int mt = 0; mt < 4; mt++) {
        int m0 = wm + mt * 16 + g;
        float bv0 = sbias[m0], bv1 = sbias[m0 + 8];
#pragma unroll
        for (int nt = 0; nt < 4; nt++) {
            int nl = wn + nt * 8 + tg * 2;
            *(float2*)(ob + (size_t)m0 * NN + nl) =
                make_float2(acc[mt][nt][0] + bv0, acc[mt][nt][1] + bv0);
            *(float2*)(ob + (size_t)(m0 + 8) * NN + nl) =
                make_float2(acc[mt][nt][2] + bv1, acc[mt][nt][3] + bv1);
        }
    }
}

// ---------------- per-head kv_state partials: 4x4 reg tiles + hoisted XOR swizzle ----------------
#define CHUNK 128
#define JSTR 36
__global__ __launch_bounds__(256)
void kvstate_kernel() {
    int bh = blockIdx.x, seg = blockIdx.y;
    int b = bh >> 3, h = bh & 7;
    const float* kbase = g_qkv + ((size_t)b * M_QKV + CC + h * HD) * NN;
    const float* vbase = g_qkv + ((size_t)b * M_QKV + 2 * CC + h * HD) * NN;
    __shared__ __align__(16) float sk[CHUNK * JSTR];
    __shared__ __align__(16) float sv[CHUNK * JSTR];
    int tid = threadIdx.x;
    int t = tid & 63, s = tid >> 6;
    int c4 = (t >> 3) * 4, d4 = (t & 7) * 4;
    int lc = tid >> 3, lj4 = (tid & 7) * 4;
    float a00=0,a01=0,a02=0,a03=0, a10=0,a11=0,a12=0,a13=0;
    float a20=0,a21=0,a22=0,a23=0, a30=0,a31=0,a32=0,a33=0;
    float ks0=0, ks1=0, ks2=0, ks3=0;
    int j_begin = seg * (NN / SEGS);

    for (int j0 = j_begin; j0 < j_begin + NN / SEGS; j0 += CHUNK) {
#pragma unroll
        for (int jj = 0; jj < CHUNK; jj += 32) {
            float4 k4 = *(const float4*)(kbase + (size_t)lc * NN + j0 + jj + lj4);
            float4 v4 = *(const float4*)(vbase + (size_t)lc * NN + j0 + jj + lj4);
            int jr = jj + lj4;
            int xv = ((jr >> 2) & 7) * 4;
            int lcs = lc ^ xv;
            sk[(jr + 0) * JSTR + lcs] = k4.x;
            sk[(jr + 1) * JSTR + lcs] = k4.y;
            sk[(jr + 2) * JSTR + lcs] = k4.z;
            sk[(jr + 3) * JSTR + lcs] = k4.w;
            sv[(jr + 0) * JSTR + lcs] = v4.x;
            sv[(jr + 1) * JSTR + lcs] = v4.y;
            sv[(jr + 2) * JSTR + lcs] = v4.z;
            sv[(jr + 3) * JSTR + lcs] = v4.w;
        }
        __syncthreads();
        int jb = s * 32;
#pragma unroll
        for (int jg = 0; jg < 32; jg += 4) {
            int jrow = jb + jg;
            int xv = ((jrow >> 2) & 7) * 4;
            const float* skp = sk + (size_t)jrow * JSTR + (c4 ^ xv);
            const float* svp = sv + (size_t)jrow * JSTR + (d4 ^ xv);
#pragma unroll
            for (int u = 0; u < 4; u++) {
                float4 kq = *(const float4*)(skp + u * JSTR);
                float4 vq = *(const float4*)(svp + u * JSTR);
                a00 += kq.x * vq.x; a01 += kq.x * vq.y; a02 += kq.x * vq.z; a03 += kq.x * vq.w;
                a10 += kq.y * vq.x; a11 += kq.y * vq.y; a12 += kq.y * vq.z; a13 += kq.y * vq.w;
                a20 += kq.z * vq.x; a21 += kq.z * vq.y; a22 += kq.z * vq.z; a23 += kq.z * vq.w;
                a30 += kq.w * vq.x; a31 += kq.w * vq.y; a32 += kq.w * vq.z; a33 += kq.w * vq.w;
                if (d4 == 0) { ks0 += kq.x; ks1 += kq.y; ks2 += kq.z; ks3 += kq.w; }
            }
        }
        __syncthreads();
    }

    float accf[16] = {a00,a01,a02,a03, a10,a11,a12,a13, a20,a21,a22,a23, a30,a31,a32,a33};
#pragma unroll
    for (int i = 0; i < 16; i++) sk[tid * 16 + i] = accf[i];
    if (d4 == 0) {
        sv[(s * 8 + (t >> 3)) * 4 + 0] = ks0;
        sv[(s * 8 + (t >> 3)) * 4 + 1] = ks1;
        sv[(s * 8 + (t >> 3)) * 4 + 2] = ks2;
        sv[(s * 8 + (t >> 3)) * 4 + 3] = ks3;
    }
    __syncthreads();
    if (tid < 64) {
        float* kvs = g_kvp + ((size_t)seg * BB * NH + bh) * HD * HD;
        int cc4 = (tid >> 3) * 4, dd4 = (tid & 7) * 4;
#pragma unroll
        for (int i = 0; i < 16; i++) {
            float r = sk[tid * 16 + i] + sk[(64 + tid) * 16 + i]
                    + sk[(128 + tid) * 16 + i] + sk[(192 + tid) * 16 + i];
            kvs[(cc4 + (i >> 2)) * HD + dd4 + (i & 3)] = r;
        }
        if ((tid & 7) == 0) {
            int gq = tid >> 3;
#pragma unroll
            for (int i = 0; i < 4; i++) {
                float r = sv[gq * 4 + i] + sv[(8 + gq) * 4 + i]
                        + sv[(16 + gq) * 4 + i] + sv[(24 + gq) * 4 + i];
                g_ksp[((size_t)seg * BB * NH + bh) * HD + cc4 + i] = r;
            }
        }
    }
}

// ---------------- fused depthwise conv + attention output (f32x2 packed) -> fp16 mid ----------------
__global__ __launch_bounds__(256)
void conv_attn_kernel(const float* __restrict__ dwc_w, const float* __restrict__ dwc_b) {
    __shared__ float skvs[HD * HD];
    __shared__ float sks[HD];
    __shared__ __align__(8) float2 tile2[2][20][21];
    __shared__ __align__(8) float2 wloc2[2][25];
    int bh = blockIdx.y;
    int b = bh >> 3, h = bh & 7;
    int ty0 = (blockIdx.x >> 2) * 16;
    int tx0 = (blockIdx.x & 3) * 16;
    int tid = threadIdx.x, lx = tid & 15, ly = tid >> 4;
    int gy = ty0 + ly, gx = tx0 + lx;
    int n = gy * WW + gx;

    for (int i = tid; i < HD * HD; i += 256) {
        float s = 0.f;
#pragma unroll
        for (int seg = 0; seg < SEGS; seg++)
            s += g_kvp[((size_t)seg * BB * NH + bh) * HD * HD + i];
        skvs[i] = s;
    }
    if (tid < HD) {
        float s = 0.f;
#pragma unroll
        for (int seg = 0; seg < SEGS; seg++)
            s += g_ksp[((size_t)seg * BB * NH + bh) * HD + tid];
        sks[tid] = s;
    }

    unsigned long long accC[16];
    const float* vball = g_qkv + ((size_t)b * M_QKV + 2 * CC + h * HD) * NN;
    for (int d0 = 0; d0 < HD; d0 += 4) {
        __syncthreads();
        if (tid < 50) {
            int p = tid / 25, i = tid % 25;
            wloc2[p][i] = make_float2(dwc_w[(d0 + 2 * p) * 25 + i],
                                      dwc_w[(d0 + 2 * p + 1) * 25 + i]);
        }
        for (int i = tid; i < 800; i += 256) {
            int p = i / 400, r = i % 400;
            int ry = r / 20, rx = r % 20;
            int sy = ty0 - 2 + ry, sx = tx0 - 2 + rx;
            float2 v = make_float2(0.f, 0.f);
            if (sy >= 0 && sy < HH && sx >= 0 && sx < WW) {
                v.x = vball[(size_t)(d0 + 2 * p) * NN + sy * WW + sx];
                v.y = vball[(size_t)(d0 + 2 * p + 1) * NN + sy * WW + sx];
            }
            tile2[p][ry][rx] = v;
        }
        __syncthreads();
#pragma unroll
        for (int p = 0; p < 2; p++) {
            unsigned long long a = pk2(dwc_b[d0 + 2 * p], dwc_b[d0 + 2 * p + 1]);
#pragma unroll
            for (int ky = 0; ky < 5; ky++)
#pragma unroll
                for (int kx = 0; kx < 5; kx++)
                    a = fma2(*(const unsigned long long*)&tile2[p][ly + ky][lx + kx],
                             *(const unsigned long long*)&wloc2[p][ky * 5 + kx], a);
            accC[d0 / 2 + p] = a;
        }
    }
    __syncthreads();

    const float* qbase = g_qkv + ((size_t)b * M_QKV + h * HD) * NN + n;
    unsigned long long acc2[16];
#pragma unroll
    for (int i = 0; i < 16; i++) acc2[i] = 0ull;
    float zacc = 0.f;
#pragma unroll
    for (int c = 0; c < HD; c++) {
        float qv = qbase[(size_t)c * NN];
        zacc += qv * sks[c];
        unsigned long long q2 = pk2(qv, qv);
        const unsigned long long* row = (const unsigned long long*)&skvs[c * HD];
#pragma unroll
        for (int d2 = 0; d2 < 16; d2++)
            acc2[d2] = fma2(q2, row[d2], acc2[d2]);
    }
    float z = 1.0f / (zacc + 1e-6f);
    unsigned long long z2 = pk2(z, z);
    __half* mh = (__half*)g_mh4;
#pragma unroll
    for (int d2 = 0; d2 < 16; d2++) {
        unsigned long long r = fma2(acc2[d2], z2, accC[d2]);
        float r0, r1;
        upk2(r, r0, r1);
        size_t off = ((size_t)b * CC + h * HD + 2 * d2) * NN + n;
        mh[off] = __float2half(r0);
        mh[off + NN] = __float2half(r1);
    }
}

// ---------------- launch ----------------
extern "C" void kernel_launch(void* const* d_in, const int* in_sizes, int n_in,
                              void* d_out, int out_size) {
    const float* x           = (const float*)d_in[0];
    const float* Wq          = (const float*)d_in[1];
    const float* bq          = (const float*)d_in[2];
    const float* Wkv         = (const float*)d_in[3];
    const float* bkv         = (const float*)d_in[4];
    const float* Wproj       = (const float*)d_in[5];
    const float* bproj       = (const float*)d_in[6];
    const float* dwc_w       = (const float*)d_in[7];
    const float* dwc_b       = (const float*)d_in[8];
    const float* scale_param = (const float*)d_in[9];
    float* out = (float*)d_out;

    float *p_qkv;
    uint4 *p_wh, *p_pwh, *p_xh, *p_mh;
    cudaGetSymbolAddress((void**)&p_qkv,  g_qkv);
    cudaGetSymbolAddress((void**)&p_wh,   g_wh4);
    cudaGetSymbolAddress((void**)&p_pwh,  g_pwh4);
    cudaGetSymbolAddress((void**)&p_xh,   g_xh4);
    cudaGetSymbolAddress((void**)&p_mh,   g_mh4);

    cudaFuncSetAttribute(gemm1_fused_kernel, cudaFuncAttributeMaxDynamicSharedMemorySize, SM_GEMM);
    cudaFuncSetAttribute(gemm2_wide_kernel, cudaFuncAttributeMaxDynamicSharedMemorySize, SM_GEMM);

    prep_kernel<<<M_QKV, CC>>>(Wq, bq, Wkv, bkv, Wproj, scale_param);

    int n4 = BB * CC * NN / 4;
    split_kernel<<<(n4 + 255) / 256, 256>>>((const float4*)x, (__half*)p_xh, n4);

    // QKV projection + focus fused: grid (32 pixel-tiles, 3 parts, 16 batches)
    gemm1_fused_kernel<<<dim3(NN / 128, 3, BB), 512, SM_GEMM>>>(
        (const __half*)p_wh, (const __half*)p_xh, p_qkv);

    kvstate_kernel<<<dim3(BB * NH, SEGS), 256>>>();

    conv_attn_kernel<<<dim3(16, BB * NH), 256>>>(dwc_w, dwc_b);

    // Output projection: 256x256 @ 256x4096 per batch -> d_out (256x128 tiles)
    gemm2_wide_kernel<<<dim3(NN / 128, 1, BB), 512, SM_GEMM>>>(
        (const __half*)p_pwh, (const __half*)p_mh, bproj, out);
}

// round 15
// speedup vs baseline: 1.1064x; 1.0425x over previous
#include <cuda_runtime.h>
#include <cuda_fp16.h>
#include <math.h>
#include <stdint.h>

#define CC 256
#define NN 4096
#define BB 16
#define NH 8
#define HD 32
#define HH 64
#define WW 64
#define M_QKV 768
#define SEGS 8

// ---------------- scratch (device globals; no allocation allowed) ----------------
__device__ float g_kvp[SEGS * BB * NH * HD * HD];  // partial kv states
__device__ float g_ksp[SEGS * BB * NH * HD];       // partial ksums
__device__ float g_bcat[M_QKV];
__device__ float g_invscale[CC];
// fp16 buffers (uint4-typed for 16B alignment)
__device__ uint4 g_wh4  [M_QKV * CC * 2 / 16];               // W fp16
__device__ uint4 g_pwh4 [CC * CC * 2 / 16];                  // Wproj fp16
__device__ uint4 g_xh4  [(size_t)BB * CC * NN * 2 / 16];     // x fp16
__device__ uint4 g_qkvh4[(size_t)BB * M_QKV * NN * 2 / 16];  // q|k|v fp16 (q,k focused)
__device__ uint4 g_mh4  [(size_t)BB * CC * NN * 2 / 16];     // mid fp16

// ---------------- ptx helpers ----------------
__device__ __forceinline__ uint32_t smem_u32(const void* p) {
    uint32_t a;
    asm("{ .reg .u64 t; cvta.to.shared.u64 t, %1; cvt.u32.u64 %0, t; }" : "=r"(a) : "l"(p));
    return a;
}
__device__ __forceinline__ void cp_async16(uint32_t saddr, const void* gptr) {
    asm volatile("cp.async.cg.shared.global [%0], [%1], 16;"
                 :: "r"(saddr), "l"(__cvta_generic_to_global(gptr)) : "memory");
}
__device__ __forceinline__ void ldsm_x4(uint32_t* r, uint32_t addr) {
    asm volatile("ldmatrix.sync.aligned.m8n8.x4.shared.b16 {%0,%1,%2,%3}, [%4];"
                 : "=r"(r[0]), "=r"(r[1]), "=r"(r[2]), "=r"(r[3]) : "r"(addr));
}
__device__ __forceinline__ void ldsm_x4_t(uint32_t* r, uint32_t addr) {
    asm volatile("ldmatrix.sync.aligned.m8n8.x4.trans.shared.b16 {%0,%1,%2,%3}, [%4];"
                 : "=r"(r[0]), "=r"(r[1]), "=r"(r[2]), "=r"(r[3]) : "r"(addr));
}
__device__ __forceinline__ void mma_f16(float* c, const uint32_t* a, uint32_t b0, uint32_t b1) {
    asm volatile(
        "mma.sync.aligned.m16n8k16.row.col.f32.f16.f16.f32 "
        "{%0,%1,%2,%3}, {%4,%5,%6,%7}, {%8,%9}, {%0,%1,%2,%3};"
        : "+f"(c[0]), "+f"(c[1]), "+f"(c[2]), "+f"(c[3])
        : "r"(a[0]), "r"(a[1]), "r"(a[2]), "r"(a[3]), "r"(b0), "r"(b1));
}
// packed fp32x2 (plain sm_100+ PTX)
__device__ __forceinline__ unsigned long long pk2(float a, float b) {
    unsigned long long r;
    asm("mov.b64 %0, {%1, %2};" : "=l"(r) : "f"(a), "f"(b));
    return r;
}
__device__ __forceinline__ void upk2(unsigned long long v, float& a, float& b) {
    asm("mov.b64 {%0, %1}, %2;" : "=f"(a), "=f"(b) : "l"(v));
}
__device__ __forceinline__ unsigned long long fma2(unsigned long long a, unsigned long long b,
                                                   unsigned long long c) {
    unsigned long long d;
    asm("fma.rn.f32x2 %0, %1, %2, %3;" : "=l"(d) : "l"(a), "l"(b), "l"(c));
    return d;
}

// ---------------- prep ----------------
__global__ void prep_kernel(const float* __restrict__ Wq, const float* __restrict__ bq,
                            const float* __restrict__ Wkv, const float* __restrict__ bkv,
                            const float* __restrict__ Wproj, const float* __restrict__ scale_param) {
    int r = blockIdx.x, t = threadIdx.x;
    float w = (r < CC) ? Wq[(size_t)r * CC + t] : Wkv[(size_t)(r - CC) * CC + t];
    ((__half*)g_wh4)[(size_t)r * CC + t] = __float2half(w);
    if (r < CC)
        ((__half*)g_pwh4)[r * CC + t] = __float2half(Wproj[(size_t)r * CC + t]);
    if (t == 0) {
        g_bcat[r] = (r < CC) ? bq[r] : bkv[r - CC];
        if (r < CC) {
            float s = scale_param[r];
            float sp = (s > 20.f) ? s : log1pf(expf(s));
            g_invscale[r] = 1.0f / sp;
        }
    }
}

// ---------------- convert fp32 -> fp16 ----------------
__global__ __launch_bounds__(256)
void split_kernel(const float4* __restrict__ src, __half* __restrict__ dst, int n4) {
    int i = blockIdx.x * 256 + threadIdx.x;
    if (i >= n4) return;
    float4 v = src[i];
    __half2* dp = (__half2*)(dst + 4 * (size_t)i);
    dp[0] = __halves2half2(__float2half(v.x), __float2half(v.y));
    dp[1] = __halves2half2(__float2half(v.z), __float2half(v.w));
}

// ================= gemm1 fused: qkv projection + in-register focus -> fp16 qkv =================
// 512 threads, CTA 256 channels x 128 pixels, 16 warps of 64x32, 3-stage ring (2 CTAs/SM).
#define P_NCHUNK 8
#define A1_STRIDE 80
#define B1_STRIDE 272
#define A1_TILE (256 * A1_STRIDE)            // 20480
#define B1_TILE (32 * B1_STRIDE)             // 8704
#define STAGE1_BYTES (A1_TILE + B1_TILE)     // 29184
#define SM_GEMM (3 * STAGE1_BYTES)           // 87552 -> 2 CTAs/SM
#define SP2O 0
#define SP6O (128 * 33 * 4)
#define SFO  (2 * 128 * 33 * 4)

__global__ __launch_bounds__(512)
void gemm1_fused_kernel(const __half* __restrict__ A, const __half* __restrict__ B,
                        __half* __restrict__ out) {
    extern __shared__ char smem[];
    __shared__ float ssinv[256], sbias[256];
    uint32_t sb = smem_u32(smem);
    int tid = threadIdx.x, lane = tid & 31, wid = tid >> 5;
    int n0 = blockIdx.x * 128;
    int part = blockIdx.y;
    int bz = blockIdx.z;
    int wm = (wid & 3) * 64;
    int wn = (wid >> 2) * 32;

    if (tid < 256) {
        sbias[tid] = g_bcat[part * 256 + tid];
        if (part < 2) ssinv[tid] = g_invscale[tid];
    }

    const __half* Am = A + (size_t)part * 256 * CC;
    const __half* Bb = B + (size_t)bz * CC * NN;

    float acc[4][4][4];
#pragma unroll
    for (int mt = 0; mt < 4; mt++)
#pragma unroll
        for (int nt = 0; nt < 4; nt++)
#pragma unroll
            for (int i = 0; i < 4; i++) acc[mt][nt][i] = 0.f;

    int a_row = tid >> 1, a_kc = (tid & 1) * 2;
    int b_row = tid >> 4, b_c = tid & 15;

    auto issue_load = [&](int ck) {
        if (ck < P_NCHUNK) {
            int kb = ck * 32;
            uint32_t st = sb + (uint32_t)(ck % 3) * STAGE1_BYTES;
            cp_async16(st + a_row * A1_STRIDE + a_kc * 16,
                       Am + (size_t)a_row * CC + kb + a_kc * 8);
            cp_async16(st + a_row * A1_STRIDE + (a_kc + 1) * 16,
                       Am + (size_t)a_row * CC + kb + (a_kc + 1) * 8);
            cp_async16(st + A1_TILE + b_row * B1_STRIDE + b_c * 16,
                       Bb + (size_t)(kb + b_row) * NN + n0 + b_c * 8);
        }
        asm volatile("cp.async.commit_group;" ::: "memory");
    };

    issue_load(0);
    issue_load(1);

    int li = lane >> 3, lr = lane & 7;

    for (int ck = 0; ck < P_NCHUNK; ck++) {
        asm volatile("cp.async.wait_group 1;" ::: "memory");
        __syncthreads();
        issue_load(ck + 2);

        uint32_t st = sb + (uint32_t)(ck % 3) * STAGE1_BYTES;
#pragma unroll
        for (int ks = 0; ks < 2; ks++) {
            uint32_t af[4][4];
#pragma unroll
            for (int mt = 0; mt < 4; mt++) {
                uint32_t addr = st + (uint32_t)(wm + mt * 16 + (li & 1) * 8 + lr) * A1_STRIDE
                                   + (uint32_t)(ks * 32 + (li >> 1) * 16);
                ldsm_x4(af[mt], addr);
            }
#pragma unroll
            for (int j = 0; j < 2; j++) {
                uint32_t addr = st + A1_TILE
                              + (uint32_t)(ks * 16 + (li & 1) * 8 + lr) * B1_STRIDE
                              + (uint32_t)(wn + j * 16 + (li >> 1) * 8) * 2;
                uint32_t t4[4];
                ldsm_x4_t(t4, addr);
#pragma unroll
                for (int mt = 0; mt < 4; mt++) {
                    mma_f16(acc[mt][2 * j],     af[mt], t4[0], t4[1]);
                    mma_f16(acc[mt][2 * j + 1], af[mt], t4[2], t4[3]);
                }
            }
        }
    }

    int g = lane >> 2, tg = lane & 3;

    if (part == 2) {
        __half* ob = out + ((size_t)bz * M_QKV + 512) * NN + n0;
#pragma unroll
        for (int mt = 0; mt < 4; mt++) {
            int m0 = wm + mt * 16 + g;
            float bv0 = sbias[m0], bv1 = sbias[m0 + 8];
#pragma unroll
            for (int nt = 0; nt < 4; nt++) {
                int nl = wn + nt * 8 + tg * 2;
                *(__half2*)(ob + (size_t)m0 * NN + nl) =
                    __floats2half2_rn(acc[mt][nt][0] + bv0, acc[mt][nt][1] + bv0);
                *(__half2*)(ob + (size_t)(m0 + 8) * NN + nl) =
                    __floats2half2_rn(acc[mt][nt][2] + bv1, acc[mt][nt][3] + bv1);
            }
        }
        return;
    }

    // q/k: in-register focus epilogue; sp2/sp6/sf overlay stage smem
    float* sp2 = (float*)(smem + SP2O);
    float* sp6 = (float*)(smem + SP6O);
    float* sf  = (float*)(smem + SFO);
    float s2l[8], s6l[8];
#pragma unroll
    for (int pl = 0; pl < 8; pl++) { s2l[pl] = 0.f; s6l[pl] = 0.f; }
#pragma unroll
    for (int mt = 0; mt < 4; mt++)
#pragma unroll
        for (int nt = 0; nt < 4; nt++)
#pragma unroll
            for (int i = 0; i < 4; i++) {
                int m = wm + mt * 16 + g + 8 * (i >> 1);
                float v = acc[mt][nt][i] + sbias[m];
                v = fmaxf(v, 0.f) + 1e-6f;
                v *= ssinv[m];
                float v3 = v * v * v;
                acc[mt][nt][i] = v3;
                int pl = nt * 2 + (i & 1);
                s2l[pl] += v * v;
                s6l[pl] += v3 * v3;
            }
    __syncthreads();
    int r = (wid & 3) * 8 + g;
#pragma unroll
    for (int pl = 0; pl < 8; pl++) {
        int p = wn + (pl >> 1) * 8 + tg * 2 + (pl & 1);
        sp2[p * 33 + r] = s2l[pl];
        sp6[p * 33 + r] = s6l[pl];
    }
    __syncthreads();
    if (tid < 128) {
        float t2 = 0.f, t6 = 0.f;
#pragma unroll
        for (int r2 = 0; r2 < 32; r2++) {
            t2 += sp2[tid * 33 + r2];
            t6 += sp6[tid * 33 + r2];
        }
        sf[tid] = sqrtf(t2 / t6);
    }
    __syncthreads();
    __half* ob = out + ((size_t)bz * M_QKV + part * 256) * NN + n0;
#pragma unroll
    for (int mt = 0; mt < 4; mt++) {
        int m0 = wm + mt * 16 + g;
#pragma unroll
        for (int nt = 0; nt < 4; nt++) {
            int p0 = wn + nt * 8 + tg * 2;
            float f0 = sf[p0], f1 = sf[p0 + 1];
            *(__half2*)(ob + (size_t)m0 * NN + p0) =
                __floats2half2_rn(acc[mt][nt][0] * f0, acc[mt][nt][1] * f1);
            *(__half2*)(ob + (size_t)(m0 + 8) * NN + p0) =
                __floats2half2_rn(acc[mt][nt][2] * f0, acc[mt][nt][3] * f1);
        }
    }
}

// ---------------- gemm2 wide: 512 threads, 256x128 tile, 3-stage ring ----------------
__global__ __launch_bounds__(512)
void gemm2_wide_kernel(const __half* __restrict__ A, const __half* __restrict__ B,
                       const float* __restrict__ bias, float* __restrict__ out) {
    extern __shared__ char smem[];
    __shared__ float sbias[256];
    uint32_t sb = smem_u32(smem);
    int tid = threadIdx.x, lane = tid & 31, wid = tid >> 5;
    int n0 = blockIdx.x * 128;
    int bz = blockIdx.z;
    int wm = (wid & 3) * 64;
    int wn = (wid >> 2) * 32;

    if (tid < 256) sbias[tid] = bias[tid];

    const __half* Bb = B + (size_t)bz * CC * NN;

    float acc[4][4][4];
#pragma unroll
    for (int mt = 0; mt < 4; mt++)
#pragma unroll
        for (int nt = 0; nt < 4; nt++)
#pragma unroll
            for (int i = 0; i < 4; i++) acc[mt][nt][i] = 0.f;

    int a_row = tid >> 1, a_kc = (tid & 1) * 2;
    int b_row = tid >> 4, b_c = tid & 15;

    auto issue_load = [&](int ck) {
        if (ck < P_NCHUNK) {
            int kb = ck * 32;
            uint32_t st = sb + (uint32_t)(ck % 3) * STAGE1_BYTES;
            cp_async16(st + a_row * A1_STRIDE + a_kc * 16,
                       A + (size_t)a_row * CC + kb + a_kc * 8);
            cp_async16(st + a_row * A1_STRIDE + (a_kc + 1) * 16,
                       A + (size_t)a_row * CC + kb + (a_kc + 1) * 8);
            cp_async16(st + A1_TILE + b_row * B1_STRIDE + b_c * 16,
                       Bb + (size_t)(kb + b_row) * NN + n0 + b_c * 8);
        }
        asm volatile("cp.async.commit_group;" ::: "memory");
    };

    issue_load(0);
    issue_load(1);

    int li = lane >> 3, lr = lane & 7;

    for (int ck = 0; ck < P_NCHUNK; ck++) {
        asm volatile("cp.async.wait_group 1;" ::: "memory");
        __syncthreads();
        issue_load(ck + 2);

        uint32_t st = sb + (uint32_t)(ck % 3) * STAGE1_BYTES;
#pragma unroll
        for (int ks = 0; ks < 2; ks++) {
            uint32_t af[4][4];
#pragma unroll
            for (int mt = 0; mt < 4; mt++) {
                uint32_t addr = st + (uint32_t)(wm + mt * 16 + (li & 1) * 8 + lr) * A1_STRIDE
                                   + (uint32_t)(ks * 32 + (li >> 1) * 16);
                ldsm_x4(af[mt], addr);
            }
#pragma unroll
            for (int j = 0; j < 2; j++) {
                uint32_t addr = st + A1_TILE
                              + (uint32_t)(ks * 16 + (li & 1) * 8 + lr) * B1_STRIDE
                              + (uint32_t)(wn + j * 16 + (li >> 1) * 8) * 2;
                uint32_t t4[4];
                ldsm_x4_t(t4, addr);
#pragma unroll
                for (int mt = 0; mt < 4; mt++) {
                    mma_f16(acc[mt][2 * j],     af[mt], t4[0], t4[1]);
                    mma_f16(acc[mt][2 * j + 1], af[mt], t4[2], t4[3]);
                }
            }
        }
    }

    int g = lane >> 2, tg = lane & 3;
    float* ob = out + (size_t)bz * CC * NN + n0;
#pragma unroll
    for (int mt = 0; mt < 4; mt++) {
        int m0 = wm + mt * 16 + g;
        float bv0 = sbias[m0], bv1 = sbias[m0 + 8];
#pragma unroll
        for (int nt = 0; nt < 4; nt++) {
            int nl = wn + nt * 8 + tg * 2;
            *(float2*)(ob + (size_t)m0 * NN + nl) =
                make_float2(acc[mt][nt][0] + bv0, acc[mt][nt][1] + bv0);
            *(float2*)(ob + (size_t)(m0 + 8) * NN + nl) =
                make_float2(acc[mt][nt][2] + bv1, acc[mt][nt][3] + bv1);
        }
    }
}

// ---------------- kv_state partials: fp16 in, 4x4 reg tiles + XOR swizzle ----------------
#define CHUNK 128
#define JSTR 36
__global__ __launch_bounds__(256)
void kvstate_kernel() {
    int bh = blockIdx.x, seg = blockIdx.y;
    int b = bh >> 3, h = bh & 7;
    const __half* qkvh = (const __half*)g_qkvh4;
    const __half* kbase = qkvh + ((size_t)b * M_QKV + CC + h * HD) * NN;
    const __half* vbase = qkvh + ((size_t)b * M_QKV + 2 * CC + h * HD) * NN;
    __shared__ __align__(16) float sk[CHUNK * JSTR];
    __shared__ __align__(16) float sv[CHUNK * JSTR];
    int tid = threadIdx.x;
    int t = tid & 63, s = tid >> 6;
    int c4 = (t >> 3) * 4, d4 = (t & 7) * 4;
    int lc = tid >> 3, lj8 = (tid & 7) * 8;      // loader: row lc, 8 consecutive j
    float a00=0,a01=0,a02=0,a03=0, a10=0,a11=0,a12=0,a13=0;
    float a20=0,a21=0,a22=0,a23=0, a30=0,a31=0,a32=0,a33=0;
    float ks0=0, ks1=0, ks2=0, ks3=0;
    int j_begin = seg * (NN / SEGS);

    for (int j0 = j_begin; j0 < j_begin + NN / SEGS; j0 += CHUNK) {
        // fp16 coalesced loads (8 halves/thread) -> XOR-swizzled fp32 j-major smem
#pragma unroll
        for (int jj = 0; jj < CHUNK; jj += 64) {
            uint4 kraw = *(const uint4*)(kbase + (size_t)lc * NN + j0 + jj + lj8);
            uint4 vraw = *(const uint4*)(vbase + (size_t)lc * NN + j0 + jj + lj8);
            const __half2* kh = (const __half2*)&kraw;
            const __half2* vh = (const __half2*)&vraw;
#pragma unroll
            for (int g2 = 0; g2 < 2; g2++) {
                int jr = jj + lj8 + g2 * 4;
                int xv = ((jr >> 2) & 7) * 4;
                int lcs = lc ^ xv;
                float2 kf0 = __half22float2(kh[g2 * 2]);
                float2 kf1 = __half22float2(kh[g2 * 2 + 1]);
                float2 vf0 = __half22float2(vh[g2 * 2]);
                float2 vf1 = __half22float2(vh[g2 * 2 + 1]);
                sk[(jr + 0) * JSTR + lcs] = kf0.x;
                sk[(jr + 1) * JSTR + lcs] = kf0.y;
                sk[(jr + 2) * JSTR + lcs] = kf1.x;
                sk[(jr + 3) * JSTR + lcs] = kf1.y;
                sv[(jr + 0) * JSTR + lcs] = vf0.x;
                sv[(jr + 1) * JSTR + lcs] = vf0.y;
                sv[(jr + 2) * JSTR + lcs] = vf1.x;
                sv[(jr + 3) * JSTR + lcs] = vf1.y;
            }
        }
        __syncthreads();
        int jb = s * 32;
#pragma unroll
        for (int jg = 0; jg < 32; jg += 4) {
            int jrow = jb + jg;
            int xv = ((jrow >> 2) & 7) * 4;
            const float* skp = sk + (size_t)jrow * JSTR + (c4 ^ xv);
            const float* svp = sv + (size_t)jrow * JSTR + (d4 ^ xv);
#pragma unroll
            for (int u = 0; u < 4; u++) {
                float4 kq = *(const float4*)(skp + u * JSTR);
                float4 vq = *(const float4*)(svp + u * JSTR);
                a00 += kq.x * vq.x; a01 += kq.x * vq.y; a02 += kq.x * vq.z; a03 += kq.x * vq.w;
                a10 += kq.y * vq.x; a11 += kq.y * vq.y; a12 += kq.y * vq.z; a13 += kq.y * vq.w;
                a20 += kq.z * vq.x; a21 += kq.z * vq.y; a22 += kq.z * vq.z; a23 += kq.z * vq.w;
                a30 += kq.w * vq.x; a31 += kq.w * vq.y; a32 += kq.w * vq.z; a33 += kq.w * vq.w;
                if (d4 == 0) { ks0 += kq.x; ks1 += kq.y; ks2 += kq.z; ks3 += kq.w; }
            }
        }
        __syncthreads();
    }

    float accf[16] = {a00,a01,a02,a03, a10,a11,a12,a13, a20,a21,a22,a23, a30,a31,a32,a33};
#pragma unroll
    for (int i = 0; i < 16; i++) sk[tid * 16 + i] = accf[i];
    if (d4 == 0) {
        sv[(s * 8 + (t >> 3)) * 4 + 0] = ks0;
        sv[(s * 8 + (t >> 3)) * 4 + 1] = ks1;
        sv[(s * 8 + (t >> 3)) * 4 + 2] = ks2;
        sv[(s * 8 + (t >> 3)) * 4 + 3] = ks3;
    }
    __syncthreads();
    if (tid < 64) {
        float* kvs = g_kvp + ((size_t)seg * BB * NH + bh) * HD * HD;
        int cc4 = (tid >> 3) * 4, dd4 = (tid & 7) * 4;
#pragma unroll
        for (int i = 0; i < 16; i++) {
            float r = sk[tid * 16 + i] + sk[(64 + tid) * 16 + i]
                    + sk[(128 + tid) * 16 + i] + sk[(192 + tid) * 16 + i];
            kvs[(cc4 + (i >> 2)) * HD + dd4 + (i & 3)] = r;
        }
        if ((tid & 7) == 0) {
            int gq = tid >> 3;
#pragma unroll
            for (int i = 0; i < 4; i++) {
                float r = sv[gq * 4 + i] + sv[(8 + gq) * 4 + i]
                        + sv[(16 + gq) * 4 + i] + sv[(24 + gq) * 4 + i];
                g_ksp[((size_t)seg * BB * NH + bh) * HD + cc4 + i] = r;
            }
        }
    }
}

// ---------------- fused depthwise conv + attention (f32x2, fp16 in) -> fp16 mid ----------------
__global__ __launch_bounds__(256)
void conv_attn_kernel(const float* __restrict__ dwc_w, const float* __restrict__ dwc_b) {
    __shared__ float skvs[HD * HD];
    __shared__ float sks[HD];
    __shared__ __align__(8) float2 tile2[2][20][21];
    __shared__ __align__(8) float2 wloc2[2][25];
    int bh = blockIdx.y;
    int b = bh >> 3, h = bh & 7;
    int ty0 = (blockIdx.x >> 2) * 16;
    int tx0 = (blockIdx.x & 3) * 16;
    int tid = threadIdx.x, lx = tid & 15, ly = tid >> 4;
    int gy = ty0 + ly, gx = tx0 + lx;
    int n = gy * WW + gx;
    const __half* qkvh = (const __half*)g_qkvh4;

    for (int i = tid; i < HD * HD; i += 256) {
        float s = 0.f;
#pragma unroll
        for (int seg = 0; seg < SEGS; seg++)
            s += g_kvp[((size_t)seg * BB * NH + bh) * HD * HD + i];
        skvs[i] = s;
    }
    if (tid < HD) {
        float s = 0.f;
#pragma unroll
        for (int seg = 0; seg < SEGS; seg++)
            s += g_ksp[((size_t)seg * BB * NH + bh) * HD + tid];
        sks[tid] = s;
    }

    unsigned long long accC[16];
    const __half* vball = qkvh + ((size_t)b * M_QKV + 2 * CC + h * HD) * NN;
    for (int d0 = 0; d0 < HD; d0 += 4) {
        __syncthreads();
        if (tid < 50) {
            int p = tid / 25, i = tid % 25;
            wloc2[p][i] = make_float2(dwc_w[(d0 + 2 * p) * 25 + i],
                                      dwc_w[(d0 + 2 * p + 1) * 25 + i]);
        }
        for (int i = tid; i < 800; i += 256) {
            int p = i / 400, r = i % 400;
            int ry = r / 20, rx = r % 20;
            int sy = ty0 - 2 + ry, sx = tx0 - 2 + rx;
            float2 v = make_float2(0.f, 0.f);
            if (sy >= 0 && sy < HH && sx >= 0 && sx < WW) {
                v.x = __half2float(vball[(size_t)(d0 + 2 * p) * NN + sy * WW + sx]);
                v.y = __half2float(vball[(size_t)(d0 + 2 * p + 1) * NN + sy * WW + sx]);
            }
            tile2[p][ry][rx] = v;
        }
        __syncthreads();
#pragma unroll
        for (int p = 0; p < 2; p++) {
            unsigned long long a = pk2(dwc_b[d0 + 2 * p], dwc_b[d0 + 2 * p + 1]);
#pragma unroll
            for (int ky = 0; ky < 5; ky++)
#pragma unroll
                for (int kx = 0; kx < 5; kx++)
                    a = fma2(*(const unsigned long long*)&tile2[p][ly + ky][lx + kx],
                             *(const unsigned long long*)&wloc2[p][ky * 5 + kx], a);
            accC[d0 / 2 + p] = a;
        }
    }
    __syncthreads();

    const __half* qbase = qkvh + ((size_t)b * M_QKV + h * HD) * NN + n;
    unsigned long long acc2[16];
#pragma unroll
    for (int i = 0; i < 16; i++) acc2[i] = 0ull;
    float zacc = 0.f;
#pragma unroll
    for (int c = 0; c < HD; c++) {
        float qv = __half2float(qbase[(size_t)c * NN]);
        zacc += qv * sks[c];
        unsigned long long q2 = pk2(qv, qv);
        const unsigned long long* row = (const unsigned long long*)&skvs[c * HD];
#pragma unroll
        for (int d2 = 0; d2 < 16; d2++)
            acc2[d2] = fma2(q2, row[d2], acc2[d2]);
    }
    float z = 1.0f / (zacc + 1e-6f);
    unsigned long long z2 = pk2(z, z);
    __half* mh = (__half*)g_mh4;
#pragma unroll
    for (int d2 = 0; d2 < 16; d2++) {
        unsigned long long r = fma2(acc2[d2], z2, accC[d2]);
        float r0, r1;
        upk2(r, r0, r1);
        size_t off = ((size_t)b * CC + h * HD + 2 * d2) * NN + n;
        mh[off] = __float2half(r0);
        mh[off + NN] = __float2half(r1);
    }
}

// ---------------- launch ----------------
extern "C" void kernel_launch(void* const* d_in, const int* in_sizes, int n_in,
                              void* d_out, int out_size) {
    const float* x           = (const float*)d_in[0];
    const float* Wq          = (const float*)d_in[1];
    const float* bq          = (const float*)d_in[2];
    const float* Wkv         = (const float*)d_in[3];
    const float* bkv         = (const float*)d_in[4];
    const float* Wproj       = (const float*)d_in[5];
    const float* bproj       = (const float*)d_in[6];
    const float* dwc_w       = (const float*)d_in[7];
    const float* dwc_b       = (const float*)d_in[8];
    const float* scale_param = (const float*)d_in[9];
    float* out = (float*)d_out;

    uint4 *p_wh, *p_pwh, *p_xh, *p_qkvh, *p_mh;
    cudaGetSymbolAddress((void**)&p_wh,   g_wh4);
    cudaGetSymbolAddress((void**)&p_pwh,  g_pwh4);
    cudaGetSymbolAddress((void**)&p_xh,   g_xh4);
    cudaGetSymbolAddress((void**)&p_qkvh, g_qkvh4);
    cudaGetSymbolAddress((void**)&p_mh,   g_mh4);

    cudaFuncSetAttribute(gemm1_fused_kernel, cudaFuncAttributeMaxDynamicSharedMemorySize, SM_GEMM);
    cudaFuncSetAttribute(gemm2_wide_kernel, cudaFuncAttributeMaxDynamicSharedMemorySize, SM_GEMM);

    prep_kernel<<<M_QKV, CC>>>(Wq, bq, Wkv, bkv, Wproj, scale_param);

    int n4 = BB * CC * NN / 4;
    split_kernel<<<(n4 + 255) / 256, 256>>>((const float4*)x, (__half*)p_xh, n4);

    // QKV projection + focus fused -> fp16 qkv: grid (32 pixel-tiles, 3 parts, 16 batches)
    gemm1_fused_kernel<<<dim3(NN / 128, 3, BB), 512, SM_GEMM>>>(
        (const __half*)p_wh, (const __half*)p_xh, (__half*)p_qkvh);

    kvstate_kernel<<<dim3(BB * NH, SEGS), 256>>>();

    conv_attn_kernel<<<dim3(16, BB * NH), 256>>>(dwc_w, dwc_b);

    // Output projection: 256x256 @ 256x4096 per batch -> d_out (256x128 tiles)
    gemm2_wide_kernel<<<dim3(NN / 128, 1, BB), 512, SM_GEMM>>>(
        (const __half*)p_pwh, (const __half*)p_mh, bproj, out);
}

// round 16
// speedup vs baseline: 1.2009x; 1.0854x over previous
#include <cuda_runtime.h>
#include <cuda_fp16.h>
#include <math.h>
#include <stdint.h>

#define CC 256
#define NN 4096
#define BB 16
#define NH 8
#define HD 32
#define HH 64
#define WW 64
#define M_QKV 768
#define KV_SEGS 4

// ---------------- scratch (device globals; no allocation allowed) ----------------
__device__ float g_kvp[KV_SEGS * BB * NH * HD * HD];  // partial kv states
__device__ float g_ksp[KV_SEGS * BB * NH * HD];       // partial ksums
__device__ float g_bcat[M_QKV];
__device__ float g_invscale[CC];
// fp16 buffers (uint4-typed for 16B alignment)
__device__ uint4 g_wh4  [M_QKV * CC * 2 / 16];               // W fp16
__device__ uint4 g_pwh4 [CC * CC * 2 / 16];                  // Wproj fp16
__device__ uint4 g_xh4  [(size_t)BB * CC * NN * 2 / 16];     // x fp16
__device__ uint4 g_qkvh4[(size_t)BB * M_QKV * NN * 2 / 16];  // q|k|v fp16 (q,k focused)
__device__ uint4 g_mh4  [(size_t)BB * CC * NN * 2 / 16];     // mid fp16

// ---------------- ptx helpers ----------------
__device__ __forceinline__ uint32_t smem_u32(const void* p) {
    uint32_t a;
    asm("{ .reg .u64 t; cvta.to.shared.u64 t, %1; cvt.u32.u64 %0, t; }" : "=r"(a) : "l"(p));
    return a;
}
__device__ __forceinline__ void cp_async16(uint32_t saddr, const void* gptr) {
    asm volatile("cp.async.cg.shared.global [%0], [%1], 16;"
                 :: "r"(saddr), "l"(__cvta_generic_to_global(gptr)) : "memory");
}
__device__ __forceinline__ void ldsm_x4(uint32_t* r, uint32_t addr) {
    asm volatile("ldmatrix.sync.aligned.m8n8.x4.shared.b16 {%0,%1,%2,%3}, [%4];"
                 : "=r"(r[0]), "=r"(r[1]), "=r"(r[2]), "=r"(r[3]) : "r"(addr));
}
__device__ __forceinline__ void ldsm_x4_t(uint32_t* r, uint32_t addr) {
    asm volatile("ldmatrix.sync.aligned.m8n8.x4.trans.shared.b16 {%0,%1,%2,%3}, [%4];"
                 : "=r"(r[0]), "=r"(r[1]), "=r"(r[2]), "=r"(r[3]) : "r"(addr));
}
__device__ __forceinline__ void mma_f16(float* c, const uint32_t* a, uint32_t b0, uint32_t b1) {
    asm volatile(
        "mma.sync.aligned.m16n8k16.row.col.f32.f16.f16.f32 "
        "{%0,%1,%2,%3}, {%4,%5,%6,%7}, {%8,%9}, {%0,%1,%2,%3};"
        : "+f"(c[0]), "+f"(c[1]), "+f"(c[2]), "+f"(c[3])
        : "r"(a[0]), "r"(a[1]), "r"(a[2]), "r"(a[3]), "r"(b0), "r"(b1));
}
// packed fp32x2 (plain sm_100+ PTX)
__device__ __forceinline__ unsigned long long pk2(float a, float b) {
    unsigned long long r;
    asm("mov.b64 %0, {%1, %2};" : "=l"(r) : "f"(a), "f"(b));
    return r;
}
__device__ __forceinline__ void upk2(unsigned long long v, float& a, float& b) {
    asm("mov.b64 {%0, %1}, %2;" : "=f"(a), "=f"(b) : "l"(v));
}
__device__ __forceinline__ unsigned long long fma2(unsigned long long a, unsigned long long b,
                                                   unsigned long long c) {
    unsigned long long d;
    asm("fma.rn.f32x2 %0, %1, %2, %3;" : "=l"(d) : "l"(a), "l"(b), "l"(c));
    return d;
}

// ---------------- prep ----------------
__global__ void prep_kernel(const float* __restrict__ Wq, const float* __restrict__ bq,
                            const float* __restrict__ Wkv, const float* __restrict__ bkv,
                            const float* __restrict__ Wproj, const float* __restrict__ scale_param) {
    int r = blockIdx.x, t = threadIdx.x;
    float w = (r < CC) ? Wq[(size_t)r * CC + t] : Wkv[(size_t)(r - CC) * CC + t];
    ((__half*)g_wh4)[(size_t)r * CC + t] = __float2half(w);
    if (r < CC)
        ((__half*)g_pwh4)[r * CC + t] = __float2half(Wproj[(size_t)r * CC + t]);
    if (t == 0) {
        g_bcat[r] = (r < CC) ? bq[r] : bkv[r - CC];
        if (r < CC) {
            float s = scale_param[r];
            float sp = (s > 20.f) ? s : log1pf(expf(s));
            g_invscale[r] = 1.0f / sp;
        }
    }
}

// ---------------- convert fp32 -> fp16 ----------------
__global__ __launch_bounds__(256)
void split_kernel(const float4* __restrict__ src, __half* __restrict__ dst, int n4) {
    int i = blockIdx.x * 256 + threadIdx.x;
    if (i >= n4) return;
    float4 v = src[i];
    __half2* dp = (__half2*)(dst + 4 * (size_t)i);
    dp[0] = __halves2half2(__float2half(v.x), __float2half(v.y));
    dp[1] = __halves2half2(__float2half(v.z), __float2half(v.w));
}

// ================= gemm1 fused: qkv projection + in-register focus -> fp16 qkv =================
#define P_NCHUNK 8
#define A1_STRIDE 80
#define B1_STRIDE 272
#define A1_TILE (256 * A1_STRIDE)            // 20480
#define B1_TILE (32 * B1_STRIDE)             // 8704
#define STAGE1_BYTES (A1_TILE + B1_TILE)     // 29184
#define SM_GEMM (3 * STAGE1_BYTES)           // 87552 -> 2 CTAs/SM
#define SP2O 0
#define SP6O (128 * 33 * 4)
#define SFO  (2 * 128 * 33 * 4)

__global__ __launch_bounds__(512)
void gemm1_fused_kernel(const __half* __restrict__ A, const __half* __restrict__ B,
                        __half* __restrict__ out) {
    extern __shared__ char smem[];
    __shared__ float ssinv[256], sbias[256];
    uint32_t sb = smem_u32(smem);
    int tid = threadIdx.x, lane = tid & 31, wid = tid >> 5;
    int n0 = blockIdx.x * 128;
    int part = blockIdx.y;
    int bz = blockIdx.z;
    int wm = (wid & 3) * 64;
    int wn = (wid >> 2) * 32;

    if (tid < 256) {
        sbias[tid] = g_bcat[part * 256 + tid];
        if (part < 2) ssinv[tid] = g_invscale[tid];
    }

    const __half* Am = A + (size_t)part * 256 * CC;
    const __half* Bb = B + (size_t)bz * CC * NN;

    float acc[4][4][4];
#pragma unroll
    for (int mt = 0; mt < 4; mt++)
#pragma unroll
        for (int nt = 0; nt < 4; nt++)
#pragma unroll
            for (int i = 0; i < 4; i++) acc[mt][nt][i] = 0.f;

    int a_row = tid >> 1, a_kc = (tid & 1) * 2;
    int b_row = tid >> 4, b_c = tid & 15;

    auto issue_load = [&](int ck) {
        if (ck < P_NCHUNK) {
            int kb = ck * 32;
            uint32_t st = sb + (uint32_t)(ck % 3) * STAGE1_BYTES;
            cp_async16(st + a_row * A1_STRIDE + a_kc * 16,
                       Am + (size_t)a_row * CC + kb + a_kc * 8);
            cp_async16(st + a_row * A1_STRIDE + (a_kc + 1) * 16,
                       Am + (size_t)a_row * CC + kb + (a_kc + 1) * 8);
            cp_async16(st + A1_TILE + b_row * B1_STRIDE + b_c * 16,
                       Bb + (size_t)(kb + b_row) * NN + n0 + b_c * 8);
        }
        asm volatile("cp.async.commit_group;" ::: "memory");
    };

    issue_load(0);
    issue_load(1);

    int li = lane >> 3, lr = lane & 7;

    for (int ck = 0; ck < P_NCHUNK; ck++) {
        asm volatile("cp.async.wait_group 1;" ::: "memory");
        __syncthreads();
        issue_load(ck + 2);

        uint32_t st = sb + (uint32_t)(ck % 3) * STAGE1_BYTES;
#pragma unroll
        for (int ks = 0; ks < 2; ks++) {
            uint32_t af[4][4];
#pragma unroll
            for (int mt = 0; mt < 4; mt++) {
                uint32_t addr = st + (uint32_t)(wm + mt * 16 + (li & 1) * 8 + lr) * A1_STRIDE
                                   + (uint32_t)(ks * 32 + (li >> 1) * 16);
                ldsm_x4(af[mt], addr);
            }
#pragma unroll
            for (int j = 0; j < 2; j++) {
                uint32_t addr = st + A1_TILE
                              + (uint32_t)(ks * 16 + (li & 1) * 8 + lr) * B1_STRIDE
                              + (uint32_t)(wn + j * 16 + (li >> 1) * 8) * 2;
                uint32_t t4[4];
                ldsm_x4_t(t4, addr);
#pragma unroll
                for (int mt = 0; mt < 4; mt++) {
                    mma_f16(acc[mt][2 * j],     af[mt], t4[0], t4[1]);
                    mma_f16(acc[mt][2 * j + 1], af[mt], t4[2], t4[3]);
                }
            }
        }
    }

    int g = lane >> 2, tg = lane & 3;

    if (part == 2) {
        __half* ob = out + ((size_t)bz * M_QKV + 512) * NN + n0;
#pragma unroll
        for (int mt = 0; mt < 4; mt++) {
            int m0 = wm + mt * 16 + g;
            float bv0 = sbias[m0], bv1 = sbias[m0 + 8];
#pragma unroll
            for (int nt = 0; nt < 4; nt++) {
                int nl = wn + nt * 8 + tg * 2;
                *(__half2*)(ob + (size_t)m0 * NN + nl) =
                    __floats2half2_rn(acc[mt][nt][0] + bv0, acc[mt][nt][1] + bv0);
                *(__half2*)(ob + (size_t)(m0 + 8) * NN + nl) =
                    __floats2half2_rn(acc[mt][nt][2] + bv1, acc[mt][nt][3] + bv1);
            }
        }
        return;
    }

    float* sp2 = (float*)(smem + SP2O);
    float* sp6 = (float*)(smem + SP6O);
    float* sf  = (float*)(smem + SFO);
    float s2l[8], s6l[8];
#pragma unroll
    for (int pl = 0; pl < 8; pl++) { s2l[pl] = 0.f; s6l[pl] = 0.f; }
#pragma unroll
    for (int mt = 0; mt < 4; mt++)
#pragma unroll
        for (int nt = 0; nt < 4; nt++)
#pragma unroll
            for (int i = 0; i < 4; i++) {
                int m = wm + mt * 16 + g + 8 * (i >> 1);
                float v = acc[mt][nt][i] + sbias[m];
                v = fmaxf(v, 0.f) + 1e-6f;
                v *= ssinv[m];
                float v3 = v * v * v;
                acc[mt][nt][i] = v3;
                int pl = nt * 2 + (i & 1);
                s2l[pl] += v * v;
                s6l[pl] += v3 * v3;
            }
    __syncthreads();
    int r = (wid & 3) * 8 + g;
#pragma unroll
    for (int pl = 0; pl < 8; pl++) {
        int p = wn + (pl >> 1) * 8 + tg * 2 + (pl & 1);
        sp2[p * 33 + r] = s2l[pl];
        sp6[p * 33 + r] = s6l[pl];
    }
    __syncthreads();
    if (tid < 128) {
        float t2 = 0.f, t6 = 0.f;
#pragma unroll
        for (int r2 = 0; r2 < 32; r2++) {
            t2 += sp2[tid * 33 + r2];
            t6 += sp6[tid * 33 + r2];
        }
        sf[tid] = sqrtf(t2 / t6);
    }
    __syncthreads();
    __half* ob = out + ((size_t)bz * M_QKV + part * 256) * NN + n0;
#pragma unroll
    for (int mt = 0; mt < 4; mt++) {
        int m0 = wm + mt * 16 + g;
#pragma unroll
        for (int nt = 0; nt < 4; nt++) {
            int p0 = wn + nt * 8 + tg * 2;
            float f0 = sf[p0], f1 = sf[p0 + 1];
            *(__half2*)(ob + (size_t)m0 * NN + p0) =
                __floats2half2_rn(acc[mt][nt][0] * f0, acc[mt][nt][1] * f1);
            *(__half2*)(ob + (size_t)(m0 + 8) * NN + p0) =
                __floats2half2_rn(acc[mt][nt][2] * f0, acc[mt][nt][3] * f1);
        }
    }
}

// ---------------- gemm2 wide: 512 threads, 256x128 tile, 3-stage ring ----------------
__global__ __launch_bounds__(512)
void gemm2_wide_kernel(const __half* __restrict__ A, const __half* __restrict__ B,
                       const float* __restrict__ bias, float* __restrict__ out) {
    extern __shared__ char smem[];
    __shared__ float sbias[256];
    uint32_t sb = smem_u32(smem);
    int tid = threadIdx.x, lane = tid & 31, wid = tid >> 5;
    int n0 = blockIdx.x * 128;
    int bz = blockIdx.z;
    int wm = (wid & 3) * 64;
    int wn = (wid >> 2) * 32;

    if (tid < 256) sbias[tid] = bias[tid];

    const __half* Bb = B + (size_t)bz * CC * NN;

    float acc[4][4][4];
#pragma unroll
    for (int mt = 0; mt < 4; mt++)
#pragma unroll
        for (int nt = 0; nt < 4; nt++)
#pragma unroll
            for (int i = 0; i < 4; i++) acc[mt][nt][i] = 0.f;

    int a_row = tid >> 1, a_kc = (tid & 1) * 2;
    int b_row = tid >> 4, b_c = tid & 15;

    auto issue_load = [&](int ck) {
        if (ck < P_NCHUNK) {
            int kb = ck * 32;
            uint32_t st = sb + (uint32_t)(ck % 3) * STAGE1_BYTES;
            cp_async16(st + a_row * A1_STRIDE + a_kc * 16,
                       A + (size_t)a_row * CC + kb + a_kc * 8);
            cp_async16(st + a_row * A1_STRIDE + (a_kc + 1) * 16,
                       A + (size_t)a_row * CC + kb + (a_kc + 1) * 8);
            cp_async16(st + A1_TILE + b_row * B1_STRIDE + b_c * 16,
                       Bb + (size_t)(kb + b_row) * NN + n0 + b_c * 8);
        }
        asm volatile("cp.async.commit_group;" ::: "memory");
    };

    issue_load(0);
    issue_load(1);

    int li = lane >> 3, lr = lane & 7;

    for (int ck = 0; ck < P_NCHUNK; ck++) {
        asm volatile("cp.async.wait_group 1;" ::: "memory");
        __syncthreads();
        issue_load(ck + 2);

        uint32_t st = sb + (uint32_t)(ck % 3) * STAGE1_BYTES;
#pragma unroll
        for (int ks = 0; ks < 2; ks++) {
            uint32_t af[4][4];
#pragma unroll
            for (int mt = 0; mt < 4; mt++) {
                uint32_t addr = st + (uint32_t)(wm + mt * 16 + (li & 1) * 8 + lr) * A1_STRIDE
                                   + (uint32_t)(ks * 32 + (li >> 1) * 16);
                ldsm_x4(af[mt], addr);
            }
#pragma unroll
            for (int j = 0; j < 2; j++) {
                uint32_t addr = st + A1_TILE
                              + (uint32_t)(ks * 16 + (li & 1) * 8 + lr) * B1_STRIDE
                              + (uint32_t)(wn + j * 16 + (li >> 1) * 8) * 2;
                uint32_t t4[4];
                ldsm_x4_t(t4, addr);
#pragma unroll
                for (int mt = 0; mt < 4; mt++) {
                    mma_f16(acc[mt][2 * j],     af[mt], t4[0], t4[1]);
                    mma_f16(acc[mt][2 * j + 1], af[mt], t4[2], t4[3]);
                }
            }
        }
    }

    int g = lane >> 2, tg = lane & 3;
    float* ob = out + (size_t)bz * CC * NN + n0;
#pragma unroll
    for (int mt = 0; mt < 4; mt++) {
        int m0 = wm + mt * 16 + g;
        float bv0 = sbias[m0], bv1 = sbias[m0 + 8];
#pragma unroll
        for (int nt = 0; nt < 4; nt++) {
            int nl = wn + nt * 8 + tg * 2;
            *(float2*)(ob + (size_t)m0 * NN + nl) =
                make_float2(acc[mt][nt][0] + bv0, acc[mt][nt][1] + bv0);
            *(float2*)(ob + (size_t)(m0 + 8) * NN + nl) =
                make_float2(acc[mt][nt][2] + bv1, acc[mt][nt][3] + bv1);
        }
    }
}

// ---------------- kv_state via mma.sync: C[32x32]=K@V^T per (b,h), ksum via ones-column ----------------
#define KCH 128
#define KSTR 272
#define KTILE (32 * KSTR)        // 8704
#define KSTAGE (2 * KTILE)       // 17408
#define SM_KV (3 * KSTAGE)       // 52224

__global__ __launch_bounds__(256)
void kvstate_kernel() {
    extern __shared__ char ksm[];
    uint32_t sb = smem_u32(ksm);
    int bh = blockIdx.x, seg = blockIdx.y;
    int b = bh >> 3, h = bh & 7;
    const __half* qkvh = (const __half*)g_qkvh4;
    const __half* kbase = qkvh + ((size_t)b * M_QKV + CC + h * HD) * NN;
    const __half* vbase = qkvh + ((size_t)b * M_QKV + 2 * CC + h * HD) * NN;
    int tid = threadIdx.x, lane = tid & 31, wid = tid >> 5;
    int j_begin = seg * (NN / KV_SEGS);

    float acc[2][5][4];
#pragma unroll
    for (int mt = 0; mt < 2; mt++)
#pragma unroll
        for (int nt = 0; nt < 5; nt++)
#pragma unroll
            for (int i = 0; i < 4; i++) acc[mt][nt][i] = 0.f;

    int r0 = (tid * 2) >> 4, c0 = (tid * 2) & 15;
    int r1 = (tid * 2 + 1) >> 4, c1 = (tid * 2 + 1) & 15;

    auto issue = [&](int ck) {
        if (ck < 8) {
            int j0 = j_begin + ck * KCH;
            uint32_t st = sb + (uint32_t)(ck % 3) * KSTAGE;
            cp_async16(st + r0 * KSTR + c0 * 16, kbase + (size_t)r0 * NN + j0 + c0 * 8);
            cp_async16(st + r1 * KSTR + c1 * 16, kbase + (size_t)r1 * NN + j0 + c1 * 8);
            cp_async16(st + KTILE + r0 * KSTR + c0 * 16, vbase + (size_t)r0 * NN + j0 + c0 * 8);
            cp_async16(st + KTILE + r1 * KSTR + c1 * 16, vbase + (size_t)r1 * NN + j0 + c1 * 8);
        }
        asm volatile("cp.async.commit_group;" ::: "memory");
    };
    issue(0);
    issue(1);

    int li = lane >> 3, lr = lane & 7;
    const uint32_t ONE2 = 0x3C003C00u;   // (1.0h, 1.0h)

    for (int ck = 0; ck < 8; ck++) {
        asm volatile("cp.async.wait_group 1;" ::: "memory");
        __syncthreads();
        issue(ck + 2);

        uint32_t st = sb + (uint32_t)(ck % 3) * KSTAGE;
        uint32_t colb = (uint32_t)wid * 32;   // warp's k16 slice (16 halves = 32B)
        uint32_t a[2][4], vb[2][4];
#pragma unroll
        for (int mt = 0; mt < 2; mt++) {
            uint32_t addr = st + (uint32_t)(mt * 16 + (li & 1) * 8 + lr) * KSTR
                               + colb + (uint32_t)(li >> 1) * 16;
            ldsm_x4(a[mt], addr);
        }
#pragma unroll
        for (int p = 0; p < 2; p++) {
            uint32_t addr = st + KTILE + (uint32_t)(p * 16 + (li >> 1) * 8 + lr) * KSTR
                               + colb + (uint32_t)(li & 1) * 16;
            ldsm_x4(vb[p], addr);
        }
#pragma unroll
        for (int mt = 0; mt < 2; mt++) {
#pragma unroll
            for (int p = 0; p < 2; p++) {
                mma_f16(acc[mt][2 * p],     a[mt], vb[p][0], vb[p][1]);
                mma_f16(acc[mt][2 * p + 1], a[mt], vb[p][2], vb[p][3]);
            }
            mma_f16(acc[mt][4], a[mt], ONE2, ONE2);   // ksum column
        }
    }

    // cross-warp reduce via smem (reuse ring: 8*1280 floats = 40KB < 52KB)
    __syncthreads();
    float* red = (float*)ksm;
#pragma unroll
    for (int mt = 0; mt < 2; mt++)
#pragma unroll
        for (int nt = 0; nt < 5; nt++)
#pragma unroll
            for (int i = 0; i < 4; i++) {
                int row = mt * 16 + (lane >> 2) + 8 * (i >> 1);
                int col = nt * 8 + (lane & 3) * 2 + (i & 1);
                red[wid * 1280 + row * 40 + col] = acc[mt][nt][i];
            }
    __syncthreads();
    for (int o = tid; o < 1280; o += 256) {
        int row = o / 40, col = o % 40;
        if (col > 32) continue;
        float s = 0.f;
#pragma unroll
        for (int w = 0; w < 8; w++) s += red[w * 1280 + o];
        if (col < 32)
            g_kvp[((size_t)seg * BB * NH + bh) * HD * HD + row * HD + col] = s;
        else
            g_ksp[((size_t)seg * BB * NH + bh) * HD + row] = s;
    }
}

// ---------------- fused depthwise conv + attention (f32x2, fp16 in) -> fp16 mid ----------------
__global__ __launch_bounds__(256)
void conv_attn_kernel(const float* __restrict__ dwc_w, const float* __restrict__ dwc_b) {
    __shared__ float skvs[HD * HD];
    __shared__ float sks[HD];
    __shared__ __align__(8) float2 tile2[2][20][21];
    __shared__ __align__(8) float2 wloc2[2][25];
    int bh = blockIdx.y;
    int b = bh >> 3, h = bh & 7;
    int ty0 = (blockIdx.x >> 2) * 16;
    int tx0 = (blockIdx.x & 3) * 16;
    int tid = threadIdx.x, lx = tid & 15, ly = tid >> 4;
    int gy = ty0 + ly, gx = tx0 + lx;
    int n = gy * WW + gx;
    const __half* qkvh = (const __half*)g_qkvh4;

    for (int i = tid; i < HD * HD; i += 256) {
        float s = 0.f;
#pragma unroll
        for (int seg = 0; seg < KV_SEGS; seg++)
            s += g_kvp[((size_t)seg * BB * NH + bh) * HD * HD + i];
        skvs[i] = s;
    }
    if (tid < HD) {
        float s = 0.f;
#pragma unroll
        for (int seg = 0; seg < KV_SEGS; seg++)
            s += g_ksp[((size_t)seg * BB * NH + bh) * HD + tid];
        sks[tid] = s;
    }

    unsigned long long accC[16];
    const __half* vball = qkvh + ((size_t)b * M_QKV + 2 * CC + h * HD) * NN;
    for (int d0 = 0; d0 < HD; d0 += 4) {
        __syncthreads();
        if (tid < 50) {
            int p = tid / 25, i = tid % 25;
            wloc2[p][i] = make_float2(dwc_w[(d0 + 2 * p) * 25 + i],
                                      dwc_w[(d0 + 2 * p + 1) * 25 + i]);
        }
        for (int i = tid; i < 800; i += 256) {
            int p = i / 400, r = i % 400;
            int ry = r / 20, rx = r % 20;
            int sy = ty0 - 2 + ry, sx = tx0 - 2 + rx;
            float2 v = make_float2(0.f, 0.f);
            if (sy >= 0 && sy < HH && sx >= 0 && sx < WW) {
                v.x = __half2float(vball[(size_t)(d0 + 2 * p) * NN + sy * WW + sx]);
                v.y = __half2float(vball[(size_t)(d0 + 2 * p + 1) * NN + sy * WW + sx]);
            }
            tile2[p][ry][rx] = v;
        }
        __syncthreads();
#pragma unroll
        for (int p = 0; p < 2; p++) {
            unsigned long long a = pk2(dwc_b[d0 + 2 * p], dwc_b[d0 + 2 * p + 1]);
#pragma unroll
            for (int ky = 0; ky < 5; ky++)
#pragma unroll
                for (int kx = 0; kx < 5; kx++)
                    a = fma2(*(const unsigned long long*)&tile2[p][ly + ky][lx + kx],
                             *(const unsigned long long*)&wloc2[p][ky * 5 + kx], a);
            accC[d0 / 2 + p] = a;
        }
    }
    __syncthreads();

    const __half* qbase = qkvh + ((size_t)b * M_QKV + h * HD) * NN + n;
    unsigned long long acc2[16];
#pragma unroll
    for (int i = 0; i < 16; i++) acc2[i] = 0ull;
    float zacc = 0.f;
#pragma unroll
    for (int c = 0; c < HD; c++) {
        float qv = __half2float(qbase[(size_t)c * NN]);
        zacc += qv * sks[c];
        unsigned long long q2 = pk2(qv, qv);
        const unsigned long long* row = (const unsigned long long*)&skvs[c * HD];
#pragma unroll
        for (int d2 = 0; d2 < 16; d2++)
            acc2[d2] = fma2(q2, row[d2], acc2[d2]);
    }
    float z = 1.0f / (zacc + 1e-6f);
    unsigned long long z2 = pk2(z, z);
    __half* mh = (__half*)g_mh4;
#pragma unroll
    for (int d2 = 0; d2 < 16; d2++) {
        unsigned long long r = fma2(acc2[d2], z2, accC[d2]);
        float r0, r1;
        upk2(r, r0, r1);
        size_t off = ((size_t)b * CC + h * HD + 2 * d2) * NN + n;
        mh[off] = __float2half(r0);
        mh[off + NN] = __float2half(r1);
    }
}

// ---------------- launch ----------------
extern "C" void kernel_launch(void* const* d_in, const int* in_sizes, int n_in,
                              void* d_out, int out_size) {
    const float* x           = (const float*)d_in[0];
    const float* Wq          = (const float*)d_in[1];
    const float* bq          = (const float*)d_in[2];
    const float* Wkv         = (const float*)d_in[3];
    const float* bkv         = (const float*)d_in[4];
    const float* Wproj       = (const float*)d_in[5];
    const float* bproj       = (const float*)d_in[6];
    const float* dwc_w       = (const float*)d_in[7];
    const float* dwc_b       = (const float*)d_in[8];
    const float* scale_param = (const float*)d_in[9];
    float* out = (float*)d_out;

    uint4 *p_wh, *p_pwh, *p_xh, *p_qkvh, *p_mh;
    cudaGetSymbolAddress((void**)&p_wh,   g_wh4);
    cudaGetSymbolAddress((void**)&p_pwh,  g_pwh4);
    cudaGetSymbolAddress((void**)&p_xh,   g_xh4);
    cudaGetSymbolAddress((void**)&p_qkvh, g_qkvh4);
    cudaGetSymbolAddress((void**)&p_mh,   g_mh4);

    cudaFuncSetAttribute(gemm1_fused_kernel, cudaFuncAttributeMaxDynamicSharedMemorySize, SM_GEMM);
    cudaFuncSetAttribute(gemm2_wide_kernel, cudaFuncAttributeMaxDynamicSharedMemorySize, SM_GEMM);
    cudaFuncSetAttribute(kvstate_kernel, cudaFuncAttributeMaxDynamicSharedMemorySize, SM_KV);

    prep_kernel<<<M_QKV, CC>>>(Wq, bq, Wkv, bkv, Wproj, scale_param);

    int n4 = BB * CC * NN / 4;
    split_kernel<<<(n4 + 255) / 256, 256>>>((const float4*)x, (__half*)p_xh, n4);

    // QKV projection + focus fused -> fp16 qkv: grid (32 pixel-tiles, 3 parts, 16 batches)
    gemm1_fused_kernel<<<dim3(NN / 128, 3, BB), 512, SM_GEMM>>>(
        (const __half*)p_wh, (const __half*)p_xh, (__half*)p_qkvh);

    kvstate_kernel<<<dim3(BB * NH, KV_SEGS), 256, SM_KV>>>();

    conv_attn_kernel<<<dim3(16, BB * NH), 256>>>(dwc_w, dwc_b);

    // Output projection: 256x256 @ 256x4096 per batch -> d_out (256x128 tiles)
    gemm2_wide_kernel<<<dim3(NN / 128, 1, BB), 512, SM_GEMM>>>(
        (const __half*)p_pwh, (const __half*)p_mh, bproj, out);
}